// round 2
// baseline (speedup 1.0000x reference)
#include <cuda_runtime.h>
#include <cuda_bf16.h>
#include <math.h>

// Problem constants
#define BB 8
#define SS 1024
#define DD 512
#define HH 8
#define DK 64
#define DFF 2048
#define LL 6
#define MM (BB*SS)          // 8192 rows
#define EPS 1e-5f
#define INV_SCALE 0.125f    // 1/sqrt(64)

// ---------------- scratch (device globals; no runtime allocation) ----------
__device__ float g_x[MM*DD];        // working activations [8192,512]
__device__ float g_qkv[MM*3*DD];    // [8192,1536]
__device__ float g_attn[MM*DD];     // attention output [8192,512]
__device__ float g_h[MM*DFF];       // MLP hidden [8192,2048]
__device__ float g_t2[MM*DD];       // pre-LN buffer [8192,512]

// ---------------- simple copy ----------------
__global__ void copy_kernel(const float* __restrict__ src, float* __restrict__ dst, int n) {
    int i = blockIdx.x * blockDim.x + threadIdx.x;
    if (i < n) dst[i] = src[i];
}

// ---------------- GEMM: C[M,N] = A[M,K] @ W[K,N] + bias (+resid) (relu?) ---
// 64x64 tile, BK=16, 256 threads, 4x4 micro-tile per thread.
template<bool RELU, bool RESID>
__global__ __launch_bounds__(256)
void gemm_kernel(const float* __restrict__ A, const float* __restrict__ W,
                 const float* __restrict__ bias, const float* __restrict__ resid,
                 float* __restrict__ C, int M, int N, int K)
{
    __shared__ float As[16][64];   // [k][m]
    __shared__ float Ws[16][64];   // [k][n]

    const int bx = blockIdx.x;     // N tile
    const int by = blockIdx.y;     // M tile
    const int tid = threadIdx.x;
    const int tx = tid & 15;
    const int ty = tid >> 4;

    const float* Ag = A + (size_t)by * 64 * K;
    const float* Wg = W + (size_t)bx * 64;

    float acc[4][4];
#pragma unroll
    for (int i = 0; i < 4; i++)
#pragma unroll
        for (int j = 0; j < 4; j++) acc[i][j] = 0.f;

    const int e  = tid * 4;
    const int ar = e >> 4, ac = e & 15;     // A tile: 64 rows x 16 cols
    const int wr = e >> 6, wc = e & 63;     // W tile: 16 rows x 64 cols

    for (int k0 = 0; k0 < K; k0 += 16) {
        float4 av = *(const float4*)(Ag + (size_t)ar * K + k0 + ac);
        float4 wv = *(const float4*)(Wg + (size_t)(k0 + wr) * N + wc);
        As[ac + 0][ar] = av.x;
        As[ac + 1][ar] = av.y;
        As[ac + 2][ar] = av.z;
        As[ac + 3][ar] = av.w;
        *(float4*)&Ws[wr][wc] = wv;
        __syncthreads();

#pragma unroll
        for (int kk = 0; kk < 16; kk++) {
            float a[4], w[4];
            *(float4*)a = *(const float4*)&As[kk][ty * 4];
            *(float4*)w = *(const float4*)&Ws[kk][tx * 4];
#pragma unroll
            for (int i = 0; i < 4; i++)
#pragma unroll
                for (int j = 0; j < 4; j++)
                    acc[i][j] = fmaf(a[i], w[j], acc[i][j]);
        }
        __syncthreads();
    }

    const int row0 = by * 64 + ty * 4;
    const int col0 = bx * 64 + tx * 4;
    float b4[4];
    *(float4*)b4 = *(const float4*)(bias + col0);

#pragma unroll
    for (int i = 0; i < 4; i++) {
        float v[4];
#pragma unroll
        for (int j = 0; j < 4; j++) {
            float t = acc[i][j] + b4[j];
            if (RESID) t += resid[(size_t)(row0 + i) * N + col0 + j];
            if (RELU)  t = fmaxf(t, 0.f);
            v[j] = t;
        }
        *(float4*)(C + (size_t)(row0 + i) * N + col0) = *(float4*)v;
    }
}

// ---------------- flash attention (causal), fp32 ----------------
// grid (S/64, H, B), block 64. One query row per thread; q,s,o in registers.
__global__ __launch_bounds__(64)
void attn_kernel(const float* __restrict__ qkv, float* __restrict__ out)
{
    const int qt = blockIdx.x;
    const int h  = blockIdx.y;
    const int b  = blockIdx.z;
    const int t  = threadIdx.x;
    const int qrow = qt * 64 + t;

    __shared__ float Ks[64][64];
    __shared__ float Vs[64][64];

    const float* qp = qkv + ((size_t)(b * SS + qrow)) * (3 * DD) + h * DK;
    float q[DK];
#pragma unroll
    for (int d = 0; d < DK; d++) q[d] = qp[d] * INV_SCALE;

    float m = -INFINITY, l = 0.f;
    float o[DK];
#pragma unroll
    for (int d = 0; d < DK; d++) o[d] = 0.f;

    for (int kt = 0; kt <= qt; kt++) {
        __syncthreads();
        // cooperative K/V tile load: column t, rows 0..63
        for (int r = 0; r < 64; r++) {
            const float* base = qkv + ((size_t)(b * SS + kt * 64 + r)) * (3 * DD) + h * DK;
            Ks[r][t] = base[DD + t];       // K
            Vs[r][t] = base[2 * DD + t];   // V
        }
        __syncthreads();

        float s[64];
        float mt = m;
        const bool diag = (kt == qt);
#pragma unroll
        for (int j = 0; j < 64; j++) {
            float acc = 0.f;
#pragma unroll
            for (int d = 0; d < DK; d++) acc = fmaf(q[d], Ks[j][d], acc);
            if (diag && (kt * 64 + j > qrow)) acc = -INFINITY;
            s[j] = acc;
            mt = fmaxf(mt, acc);
        }
        const float c = __expf(m - mt);
        m = mt;
        l *= c;
#pragma unroll
        for (int d = 0; d < DK; d++) o[d] *= c;

#pragma unroll
        for (int j = 0; j < 64; j++) {
            const float p = __expf(s[j] - m);   // masked -> exp(-inf)=0
            l += p;
#pragma unroll
            for (int d = 0; d < DK; d++) o[d] = fmaf(p, Vs[j][d], o[d]);
        }
    }

    const float inv_l = 1.f / l;
    float* op = out + ((size_t)(b * SS + qrow)) * DD + h * DK;
#pragma unroll
    for (int d = 0; d < DK; d++) op[d] = o[d] * inv_l;
}

// ---------------- LayerNorm: one row (512) per block, 256 threads ---------
__global__ __launch_bounds__(256)
void ln_kernel(const float* __restrict__ in, const float* __restrict__ gamma,
               const float* __restrict__ beta, float* __restrict__ out)
{
    const int row = blockIdx.x;
    const int t = threadIdx.x;
    const float* xr = in + (size_t)row * DD;

    const float x0 = xr[t];
    const float x1 = xr[t + 256];
    float s  = x0 + x1;
    float sq = x0 * x0 + x1 * x1;

#pragma unroll
    for (int off = 16; off > 0; off >>= 1) {
        s  += __shfl_xor_sync(0xffffffffu, s,  off);
        sq += __shfl_xor_sync(0xffffffffu, sq, off);
    }
    __shared__ float ss[8], sqq[8];
    if ((t & 31) == 0) { ss[t >> 5] = s; sqq[t >> 5] = sq; }
    __syncthreads();
    float ts = 0.f, tq = 0.f;
#pragma unroll
    for (int w = 0; w < 8; w++) { ts += ss[w]; tq += sqq[w]; }

    const float mean = ts * (1.f / DD);
    const float var  = tq * (1.f / DD) - mean * mean;
    const float rstd = rsqrtf(var + EPS);

    float* orow = out + (size_t)row * DD;
    orow[t]       = (x0 - mean) * rstd * gamma[t]       + beta[t];
    orow[t + 256] = (x1 - mean) * rstd * gamma[t + 256] + beta[t + 256];
}

// ---------------- driver ----------------
extern "C" void kernel_launch(void* const* d_in, const int* in_sizes, int n_in,
                              void* d_out, int out_size)
{
    const float* x      = (const float*)d_in[0];
    const float* qkv_w  = (const float*)d_in[1];   // [6,512,1536]
    const float* qkv_b  = (const float*)d_in[2];   // [6,1536]
    const float* out_w  = (const float*)d_in[3];   // [6,512,512]
    const float* out_b  = (const float*)d_in[4];   // [6,512]
    const float* ln1_g  = (const float*)d_in[5];   // [6,512]
    const float* ln1_b  = (const float*)d_in[6];
    const float* mlp_w1 = (const float*)d_in[7];   // [6,512,2048]
    const float* mlp_b1 = (const float*)d_in[8];   // [6,2048]
    const float* mlp_w2 = (const float*)d_in[9];   // [6,2048,512]
    const float* mlp_b2 = (const float*)d_in[10];  // [6,512]
    const float* ln2_g  = (const float*)d_in[11];
    const float* ln2_b  = (const float*)d_in[12];
    float* outp = (float*)d_out;

    float *px, *pqkv, *pattn, *ph, *pt2;
    cudaGetSymbolAddress((void**)&px,   g_x);
    cudaGetSymbolAddress((void**)&pqkv, g_qkv);
    cudaGetSymbolAddress((void**)&pattn,g_attn);
    cudaGetSymbolAddress((void**)&ph,   g_h);
    cudaGetSymbolAddress((void**)&pt2,  g_t2);

    const int nX = MM * DD;
    copy_kernel<<<(nX + 255) / 256, 256>>>(x, px, nX);

    for (int i = 0; i < LL; i++) {
        // QKV projection: [8192,512] x [512,1536]
        gemm_kernel<false, false><<<dim3(3 * DD / 64, MM / 64), 256>>>(
            px, qkv_w + (size_t)i * DD * 3 * DD, qkv_b + (size_t)i * 3 * DD,
            nullptr, pqkv, MM, 3 * DD, DD);

        // causal flash attention
        attn_kernel<<<dim3(SS / 64, HH, BB), 64>>>(pqkv, pattn);

        // out projection + residual: [8192,512] x [512,512] + x
        gemm_kernel<false, true><<<dim3(DD / 64, MM / 64), 256>>>(
            pattn, out_w + (size_t)i * DD * DD, out_b + (size_t)i * DD,
            px, pt2, MM, DD, DD);

        // LN1 -> x
        ln_kernel<<<MM, 256>>>(pt2, ln1_g + (size_t)i * DD, ln1_b + (size_t)i * DD, px);

        // MLP1 + ReLU: [8192,512] x [512,2048]
        gemm_kernel<true, false><<<dim3(DFF / 64, MM / 64), 256>>>(
            px, mlp_w1 + (size_t)i * DD * DFF, mlp_b1 + (size_t)i * DFF,
            nullptr, ph, MM, DFF, DD);

        // MLP2 + residual: [8192,2048] x [2048,512] + x
        gemm_kernel<false, true><<<dim3(DD / 64, MM / 64), 256>>>(
            ph, mlp_w2 + (size_t)i * DFF * DD, mlp_b2 + (size_t)i * DD,
            px, pt2, MM, DD, DFF);

        // LN2 -> x
        ln_kernel<<<MM, 256>>>(pt2, ln2_g + (size_t)i * DD, ln2_b + (size_t)i * DD, px);
    }

    copy_kernel<<<(nX + 255) / 256, 256>>>(px, outp, nX);
}

// round 4
// speedup vs baseline: 1.8342x; 1.8342x over previous
#include <cuda_runtime.h>
#include <cuda_bf16.h>
#include <math.h>
#include <cstdint>

// Problem constants
#define BB 8
#define SS 1024
#define DD 512
#define HH 8
#define DK 64
#define DFF 2048
#define LL 6
#define MM (BB*SS)          // 8192 rows
#define EPS 1e-5f
#define INV_SCALE 0.125f

// GEMM tiling
#define BM 128
#define BN 128
#define BKC 32              // K elements per chunk
#define LDS_STRIDE 36       // floats per smem row (conflict-free, 16B-aligned)
#define TILE_FLOATS (128*LDS_STRIDE)          // 4608 floats per operand tile
#define TILE_BYTES  (TILE_FLOATS*4)           // 18432 B
#define BUF_FLOATS  (2*TILE_FLOATS)           // A+B per buffer
#define GSMEM_BYTES (2*2*TILE_BYTES)          // double buffered A+B = 73728

// ---------------- scratch (device globals; no runtime allocation) ----------
__device__ float g_x[MM*DD];           // exact fp32 activations
__device__ float g_xr[MM*DD];          // tf32-rounded copy (GEMM A operand)
__device__ float g_qkv[MM*3*DD];
__device__ float g_attn[MM*DD];
__device__ float g_attnr[MM*DD];
__device__ float g_h[MM*DFF];          // tf32-rounded (MLP1 epilogue)
__device__ float g_t2[MM*DD];
// transposed (+tf32-rounded) weights, [N,K] K-major
__device__ float g_qkv_wt[LL*3*DD*DD];
__device__ float g_out_wt[LL*DD*DD];
__device__ float g_w1t[LL*DFF*DD];
__device__ float g_w2t[LL*DD*DFF];

// ---------------- small helpers ----------------
__device__ __forceinline__ float tf32r(float x) {
    uint32_t u; asm("cvt.rna.tf32.f32 %0, %1;" : "=r"(u) : "f"(x));
    return __uint_as_float(u);
}
__device__ __forceinline__ uint32_t smem_u32(const void* p) {
    uint32_t a;
    asm("{ .reg .u64 t; cvta.to.shared.u64 t, %1; cvt.u32.u64 %0, t; }" : "=r"(a) : "l"(p));
    return a;
}
__device__ __forceinline__ void cp_async16(uint32_t dst, const void* src) {
    asm volatile("cp.async.cg.shared.global [%0], [%1], 16;" :: "r"(dst), "l"(src));
}
__device__ __forceinline__ void cp_commit() {
    asm volatile("cp.async.commit_group;" ::: "memory");
}

// ---------------- elementwise kernels ----------------
__global__ void copy_kernel(const float* __restrict__ src, float* __restrict__ dst, int n) {
    int i = blockIdx.x * blockDim.x + threadIdx.x;
    if (i < n) dst[i] = src[i];
}
__global__ void copy_round_kernel(const float4* __restrict__ src, float4* __restrict__ dst,
                                  float4* __restrict__ dstr, int n4) {
    int i = blockIdx.x * blockDim.x + threadIdx.x;
    if (i < n4) {
        float4 v = src[i];
        dst[i] = v;
        dstr[i] = make_float4(tf32r(v.x), tf32r(v.y), tf32r(v.z), tf32r(v.w));
    }
}
__global__ void round_kernel(const float4* __restrict__ src, float4* __restrict__ dst, int n4) {
    int i = blockIdx.x * blockDim.x + threadIdx.x;
    if (i < n4) {
        float4 v = src[i];
        dst[i] = make_float4(tf32r(v.x), tf32r(v.y), tf32r(v.z), tf32r(v.w));
    }
}

// transpose + tf32-round: W[L][K][N] -> Wt[L][N][K]
__global__ void transpose_rnd(const float* __restrict__ W, float* __restrict__ Wt,
                              int K, int N) {
    __shared__ float t[32][33];
    const int l = blockIdx.z;
    const float* Wl = W + (size_t)l * K * N;
    float* Wtl = Wt + (size_t)l * K * N;
    const int k0 = blockIdx.y * 32, n0 = blockIdx.x * 32;
    const int tx = threadIdx.x, ty = threadIdx.y;   // 32 x 8
#pragma unroll
    for (int i = 0; i < 32; i += 8)
        t[ty + i][tx] = Wl[(size_t)(k0 + ty + i) * N + n0 + tx];
    __syncthreads();
#pragma unroll
    for (int i = 0; i < 32; i += 8)
        Wtl[(size_t)(n0 + ty + i) * K + k0 + tx] = tf32r(t[tx][ty + i]);
}

// ---------------- tf32 mma.sync GEMM: C[M,N] = A[M,K] @ Wt[N,K]^T ----------
// A and Wt pre-rounded to tf32. 128x128 CTA tile, K-chunks of 32,
// cp.async double-buffered. 8 warps, 64x32 warp tile, m16n8k8 fragments.
template<bool RELU, bool RESID, bool RND>
__global__ __launch_bounds__(256)
void tc_gemm(const float* __restrict__ A, const float* __restrict__ Bw,
             const float* __restrict__ bias, const float* __restrict__ resid,
             float* __restrict__ C, int M, int N, int K)
{
    extern __shared__ float smemf[];
    const uint32_t sb = smem_u32(smemf);

    const int tid = threadIdx.x;
    const int wid = tid >> 5;
    const int lane = tid & 31;
    const int bx = blockIdx.x, by = blockIdx.y;

    const float* Ag = A + (size_t)by * BM * K;
    const float* Bg = Bw + (size_t)bx * BN * K;

    // global->smem mapping: 1024 float4 per operand tile; thread does 4 A + 4 B
    const int grow = tid >> 3;          // 0..31 (row group)
    const int gc4  = tid & 7;           // float4 column within 32-float row

    auto issue_chunk = [&](int chunk, int buf) {
        const int k0 = chunk * BKC;
        const uint32_t base = sb + (uint32_t)buf * (2u * TILE_BYTES);
#pragma unroll
        for (int p = 0; p < 4; p++) {
            const int r = p * 32 + grow;
            cp_async16(base + (uint32_t)r * (LDS_STRIDE*4) + (uint32_t)gc4 * 16,
                       Ag + (size_t)r * K + k0 + gc4 * 4);
        }
#pragma unroll
        for (int p = 0; p < 4; p++) {
            const int r = p * 32 + grow;
            cp_async16(base + TILE_BYTES + (uint32_t)r * (LDS_STRIDE*4) + (uint32_t)gc4 * 16,
                       Bg + (size_t)r * K + k0 + gc4 * 4);
        }
        cp_commit();
    };

    const int nc = K / BKC;
    issue_chunk(0, 0);
    if (nc > 1) issue_chunk(1, 1);

    // warp tile: 64 rows x 32 cols
    const int wm = (wid >> 2) * 64;
    const int wn = (wid & 3) * 32;
    const int qr = lane >> 2;   // 0..7
    const int qc = lane & 3;    // 0..3

    float acc[4][4][4];
#pragma unroll
    for (int mi = 0; mi < 4; mi++)
#pragma unroll
        for (int ni = 0; ni < 4; ni++)
#pragma unroll
            for (int e = 0; e < 4; e++) acc[mi][ni][e] = 0.f;

    for (int c = 0; c < nc; c++) {
        if (c + 1 < nc) asm volatile("cp.async.wait_group 1;" ::: "memory");
        else            asm volatile("cp.async.wait_group 0;" ::: "memory");
        __syncthreads();

        const uint32_t* sAu = reinterpret_cast<const uint32_t*>(smemf) + (c & 1) * BUF_FLOATS;
        const uint32_t* sBu = sAu + TILE_FLOATS;

#pragma unroll
        for (int ks = 0; ks < 4; ks++) {
            const int kk = ks * 8 + qc;
            uint32_t bfr[4][2];
#pragma unroll
            for (int ni = 0; ni < 4; ni++) {
                const int n = wn + ni * 8 + qr;
                bfr[ni][0] = sBu[n * LDS_STRIDE + kk];
                bfr[ni][1] = sBu[n * LDS_STRIDE + kk + 4];
            }
#pragma unroll
            for (int mi = 0; mi < 4; mi++) {
                const int r = wm + mi * 16 + qr;
                const uint32_t a0 = sAu[r * LDS_STRIDE + kk];
                const uint32_t a1 = sAu[(r + 8) * LDS_STRIDE + kk];
                const uint32_t a2 = sAu[r * LDS_STRIDE + kk + 4];
                const uint32_t a3 = sAu[(r + 8) * LDS_STRIDE + kk + 4];
#pragma unroll
                for (int ni = 0; ni < 4; ni++) {
                    asm volatile(
                        "mma.sync.aligned.m16n8k8.row.col.f32.tf32.tf32.f32 "
                        "{%0,%1,%2,%3}, {%4,%5,%6,%7}, {%8,%9}, {%0,%1,%2,%3};"
                        : "+f"(acc[mi][ni][0]), "+f"(acc[mi][ni][1]),
                          "+f"(acc[mi][ni][2]), "+f"(acc[mi][ni][3])
                        : "r"(a0), "r"(a1), "r"(a2), "r"(a3),
                          "r"(bfr[ni][0]), "r"(bfr[ni][1]));
                }
            }
        }
        __syncthreads();
        if (c + 2 < nc) issue_chunk(c + 2, c & 1);
    }

    // epilogue: bias (+resid) (relu) (tf32-round), vectorized float2 stores
#pragma unroll
    for (int mi = 0; mi < 4; mi++) {
#pragma unroll
        for (int ni = 0; ni < 4; ni++) {
            const int r0 = by * BM + wm + mi * 16 + qr;
            const int c0 = bx * BN + wn + ni * 8 + qc * 2;
            const float2 bv = *(const float2*)(bias + c0);
#pragma unroll
            for (int hrow = 0; hrow < 2; hrow++) {
                const int rr = r0 + hrow * 8;
                float v0 = acc[mi][ni][hrow * 2 + 0] + bv.x;
                float v1 = acc[mi][ni][hrow * 2 + 1] + bv.y;
                if (RESID) {
                    const float2 rv = *(const float2*)(resid + (size_t)rr * N + c0);
                    v0 += rv.x; v1 += rv.y;
                }
                if (RELU) { v0 = fmaxf(v0, 0.f); v1 = fmaxf(v1, 0.f); }
                if (RND)  { v0 = tf32r(v0); v1 = tf32r(v1); }
                *(float2*)(C + (size_t)rr * N + c0) = make_float2(v0, v1);
            }
        }
    }
}

// ---------------- flash attention (causal), fp32 ----------------
__global__ __launch_bounds__(64)
void attn_kernel(const float* __restrict__ qkv, float* __restrict__ out)
{
    const int qt = blockIdx.x;
    const int h  = blockIdx.y;
    const int b  = blockIdx.z;
    const int t  = threadIdx.x;
    const int qrow = qt * 64 + t;

    __shared__ float Ks[64][64];
    __shared__ float Vs[64][64];

    const float* qp = qkv + ((size_t)(b * SS + qrow)) * (3 * DD) + h * DK;
    float q[DK];
#pragma unroll
    for (int d = 0; d < DK; d++) q[d] = qp[d] * INV_SCALE;

    float m = -INFINITY, l = 0.f;
    float o[DK];
#pragma unroll
    for (int d = 0; d < DK; d++) o[d] = 0.f;

    for (int kt = 0; kt <= qt; kt++) {
        __syncthreads();
        for (int r = 0; r < 64; r++) {
            const float* base = qkv + ((size_t)(b * SS + kt * 64 + r)) * (3 * DD) + h * DK;
            Ks[r][t] = base[DD + t];
            Vs[r][t] = base[2 * DD + t];
        }
        __syncthreads();

        float s[64];
        float mt = m;
        const bool diag = (kt == qt);
#pragma unroll
        for (int jj = 0; jj < 64; jj++) {
            float a = 0.f;
#pragma unroll
            for (int d = 0; d < DK; d++) a = fmaf(q[d], Ks[jj][d], a);
            if (diag && (kt * 64 + jj > qrow)) a = -INFINITY;
            s[jj] = a;
            mt = fmaxf(mt, a);
        }
        const float cc = __expf(m - mt);
        m = mt;
        l *= cc;
#pragma unroll
        for (int d = 0; d < DK; d++) o[d] *= cc;

#pragma unroll
        for (int jj = 0; jj < 64; jj++) {
            const float p = __expf(s[jj] - m);
            l += p;
#pragma unroll
            for (int d = 0; d < DK; d++) o[d] = fmaf(p, Vs[jj][d], o[d]);
        }
    }

    const float inv_l = 1.f / l;
    float* op = out + ((size_t)(b * SS + qrow)) * DD + h * DK;
#pragma unroll
    for (int d = 0; d < DK; d++) op[d] = o[d] * inv_l;
}

// ---------------- LayerNorm: dual output (exact fp32 + tf32-rounded) -------
__global__ __launch_bounds__(256)
void ln_kernel(const float* __restrict__ in, const float* __restrict__ gamma,
               const float* __restrict__ beta, float* __restrict__ out,
               float* __restrict__ outr)
{
    const int row = blockIdx.x;
    const int t = threadIdx.x;
    const float* xr = in + (size_t)row * DD;

    const float x0 = xr[t];
    const float x1 = xr[t + 256];
    float s  = x0 + x1;
    float sq = x0 * x0 + x1 * x1;

#pragma unroll
    for (int off = 16; off > 0; off >>= 1) {
        s  += __shfl_xor_sync(0xffffffffu, s,  off);
        sq += __shfl_xor_sync(0xffffffffu, sq, off);
    }
    __shared__ float ss[8], sqq[8];
    if ((t & 31) == 0) { ss[t >> 5] = s; sqq[t >> 5] = sq; }
    __syncthreads();
    float ts = 0.f, tq = 0.f;
#pragma unroll
    for (int w = 0; w < 8; w++) { ts += ss[w]; tq += sqq[w]; }

    const float mean = ts * (1.f / DD);
    const float var  = tq * (1.f / DD) - mean * mean;
    const float rstd = rsqrtf(var + EPS);

    float* orow = out + (size_t)row * DD;
    float* orr  = outr + (size_t)row * DD;
    const float v0 = (x0 - mean) * rstd * gamma[t]       + beta[t];
    const float v1 = (x1 - mean) * rstd * gamma[t + 256] + beta[t + 256];
    orow[t]       = v0;
    orow[t + 256] = v1;
    orr[t]        = tf32r(v0);
    orr[t + 256]  = tf32r(v1);
}

// ---------------- driver ----------------
extern "C" void kernel_launch(void* const* d_in, const int* in_sizes, int n_in,
                              void* d_out, int out_size)
{
    const float* x      = (const float*)d_in[0];
    const float* qkv_w  = (const float*)d_in[1];   // [6,512,1536]
    const float* qkv_b  = (const float*)d_in[2];
    const float* out_w  = (const float*)d_in[3];   // [6,512,512]
    const float* out_b  = (const float*)d_in[4];
    const float* ln1_g  = (const float*)d_in[5];
    const float* ln1_b  = (const float*)d_in[6];
    const float* mlp_w1 = (const float*)d_in[7];   // [6,512,2048]
    const float* mlp_b1 = (const float*)d_in[8];
    const float* mlp_w2 = (const float*)d_in[9];   // [6,2048,512]
    const float* mlp_b2 = (const float*)d_in[10];
    const float* ln2_g  = (const float*)d_in[11];
    const float* ln2_b  = (const float*)d_in[12];
    float* outp = (float*)d_out;

    float *px, *pxr, *pqkv, *pattn, *pattnr, *ph, *pt2;
    float *pqkvwt, *poutwt, *pw1t, *pw2t;
    cudaGetSymbolAddress((void**)&px,    g_x);
    cudaGetSymbolAddress((void**)&pxr,   g_xr);
    cudaGetSymbolAddress((void**)&pqkv,  g_qkv);
    cudaGetSymbolAddress((void**)&pattn, g_attn);
    cudaGetSymbolAddress((void**)&pattnr,g_attnr);
    cudaGetSymbolAddress((void**)&ph,    g_h);
    cudaGetSymbolAddress((void**)&pt2,   g_t2);
    cudaGetSymbolAddress((void**)&pqkvwt,g_qkv_wt);
    cudaGetSymbolAddress((void**)&poutwt,g_out_wt);
    cudaGetSymbolAddress((void**)&pw1t,  g_w1t);
    cudaGetSymbolAddress((void**)&pw2t,  g_w2t);

    cudaFuncSetAttribute(tc_gemm<false,false,false>, cudaFuncAttributeMaxDynamicSharedMemorySize, GSMEM_BYTES);
    cudaFuncSetAttribute(tc_gemm<false,true,false>,  cudaFuncAttributeMaxDynamicSharedMemorySize, GSMEM_BYTES);
    cudaFuncSetAttribute(tc_gemm<true,false,true>,   cudaFuncAttributeMaxDynamicSharedMemorySize, GSMEM_BYTES);

    // weight transposes (+tf32 round), once per launch
    transpose_rnd<<<dim3(3*DD/32, DD/32, LL), dim3(32,8)>>>(qkv_w, pqkvwt, DD, 3*DD);
    transpose_rnd<<<dim3(DD/32,   DD/32, LL), dim3(32,8)>>>(out_w, poutwt, DD, DD);
    transpose_rnd<<<dim3(DFF/32,  DD/32, LL), dim3(32,8)>>>(mlp_w1, pw1t, DD, DFF);
    transpose_rnd<<<dim3(DD/32,  DFF/32, LL), dim3(32,8)>>>(mlp_w2, pw2t, DFF, DD);

    const int nX = MM * DD;
    copy_round_kernel<<<(nX/4 + 255)/256, 256>>>((const float4*)x, (float4*)px, (float4*)pxr, nX/4);

    for (int i = 0; i < LL; i++) {
        // QKV: [8192,512] x [512,1536] (+bias)
        tc_gemm<false,false,false><<<dim3(3*DD/BN, MM/BM), 256, GSMEM_BYTES>>>(
            pxr, pqkvwt + (size_t)i * 3*DD*DD, qkv_b + (size_t)i * 3*DD,
            nullptr, pqkv, MM, 3*DD, DD);

        attn_kernel<<<dim3(SS/64, HH, BB), 64>>>(pqkv, pattn);
        round_kernel<<<(nX/4 + 255)/256, 256>>>((const float4*)pattn, (float4*)pattnr, nX/4);

        // out-proj + residual(x)
        tc_gemm<false,true,false><<<dim3(DD/BN, MM/BM), 256, GSMEM_BYTES>>>(
            pattnr, poutwt + (size_t)i * DD*DD, out_b + (size_t)i * DD,
            px, pt2, MM, DD, DD);

        ln_kernel<<<MM, 256>>>(pt2, ln1_g + (size_t)i * DD, ln1_b + (size_t)i * DD, px, pxr);

        // MLP1 + ReLU, output tf32-rounded
        tc_gemm<true,false,true><<<dim3(DFF/BN, MM/BM), 256, GSMEM_BYTES>>>(
            pxr, pw1t + (size_t)i * DFF*DD, mlp_b1 + (size_t)i * DFF,
            nullptr, ph, MM, DFF, DD);

        // MLP2 + residual(x)
        tc_gemm<false,true,false><<<dim3(DD/BN, MM/BM), 256, GSMEM_BYTES>>>(
            ph, pw2t + (size_t)i * DD*DFF, mlp_b2 + (size_t)i * DD,
            px, pt2, MM, DD, DFF);

        ln_kernel<<<MM, 256>>>(pt2, ln2_g + (size_t)i * DD, ln2_b + (size_t)i * DD, px, pxr);
    }

    copy_kernel<<<(nX + 255)/256, 256>>>(px, outp, nX);
}

// round 5
// speedup vs baseline: 4.2081x; 2.2943x over previous
#include <cuda_runtime.h>
#include <cuda_bf16.h>
#include <math.h>
#include <cstdint>

// Problem constants
#define BB 8
#define SS 1024
#define DD 512
#define HH 8
#define DK 64
#define DFF 2048
#define LL 6
#define MM (BB*SS)          // 8192 rows
#define EPS 1e-5f
#define INV_SCALE 0.125f

// GEMM tiling
#define BM 128
#define BN 128
#define BKC 32
#define LDS_STRIDE 36
#define TILE_FLOATS (128*LDS_STRIDE)
#define TILE_BYTES  (TILE_FLOATS*4)
#define BUF_FLOATS  (2*TILE_FLOATS)
#define GSMEM_BYTES (2*2*TILE_BYTES)          // 73728

// Attention smem layout (floats)
#define AQ_STRIDE 68
#define AV_STRIDE 72
#define SQ_OFF  0                        // 128*68 = 8704
#define SK_OFF  8704                     // 64*68  = 4352
#define SKL_OFF 13056                    // 64*68  = 4352
#define SV_OFF  17408                    // 64*72  = 4608
#define SP_OFF  22016                    // 8*16*68 = 8704
#define ASMEM_FLOATS 30720
#define ASMEM_BYTES (ASMEM_FLOATS*4)     // 122880

// ---------------- scratch ----------------
__device__ float g_x[MM*DD];
__device__ float g_xr[MM*DD];
__device__ float g_qkv[MM*3*DD];
__device__ float g_attnr[MM*DD];         // tf32-rounded attention output
__device__ float g_h[MM*DFF];
__device__ float g_t2[MM*DD];
__device__ float g_qkv_wt[LL*3*DD*DD];
__device__ float g_out_wt[LL*DD*DD];
__device__ float g_w1t[LL*DFF*DD];
__device__ float g_w2t[LL*DD*DFF];

// ---------------- helpers ----------------
__device__ __forceinline__ float tf32r(float x) {
    uint32_t u; asm("cvt.rna.tf32.f32 %0, %1;" : "=r"(u) : "f"(x));
    return __uint_as_float(u);
}
__device__ __forceinline__ uint32_t smem_u32(const void* p) {
    uint32_t a;
    asm("{ .reg .u64 t; cvta.to.shared.u64 t, %1; cvt.u32.u64 %0, t; }" : "=r"(a) : "l"(p));
    return a;
}
__device__ __forceinline__ void cp_async16(uint32_t dst, const void* src) {
    asm volatile("cp.async.cg.shared.global [%0], [%1], 16;" :: "r"(dst), "l"(src));
}
__device__ __forceinline__ void cp_commit() {
    asm volatile("cp.async.commit_group;" ::: "memory");
}
__device__ __forceinline__ void mma8(float c[4], const float a0, const float a1,
                                     const float a2, const float a3,
                                     const float b0, const float b1) {
    asm volatile(
        "mma.sync.aligned.m16n8k8.row.col.f32.tf32.tf32.f32 "
        "{%0,%1,%2,%3}, {%4,%5,%6,%7}, {%8,%9}, {%0,%1,%2,%3};"
        : "+f"(c[0]), "+f"(c[1]), "+f"(c[2]), "+f"(c[3])
        : "r"(__float_as_uint(a0)), "r"(__float_as_uint(a1)),
          "r"(__float_as_uint(a2)), "r"(__float_as_uint(a3)),
          "r"(__float_as_uint(b0)), "r"(__float_as_uint(b1)));
}

// ---------------- elementwise ----------------
__global__ void copy_round_kernel(const float4* __restrict__ src, float4* __restrict__ dst,
                                  float4* __restrict__ dstr, int n4) {
    int i = blockIdx.x * blockDim.x + threadIdx.x;
    if (i < n4) {
        float4 v = src[i];
        dst[i] = v;
        dstr[i] = make_float4(tf32r(v.x), tf32r(v.y), tf32r(v.z), tf32r(v.w));
    }
}

// transpose + tf32-round: W[L][K][N] -> Wt[L][N][K]
__global__ void transpose_rnd(const float* __restrict__ W, float* __restrict__ Wt,
                              int K, int N) {
    __shared__ float t[32][33];
    const int l = blockIdx.z;
    const float* Wl = W + (size_t)l * K * N;
    float* Wtl = Wt + (size_t)l * K * N;
    const int k0 = blockIdx.y * 32, n0 = blockIdx.x * 32;
    const int tx = threadIdx.x, ty = threadIdx.y;
#pragma unroll
    for (int i = 0; i < 32; i += 8)
        t[ty + i][tx] = Wl[(size_t)(k0 + ty + i) * N + n0 + tx];
    __syncthreads();
#pragma unroll
    for (int i = 0; i < 32; i += 8)
        Wtl[(size_t)(n0 + ty + i) * K + k0 + tx] = tf32r(t[tx][ty + i]);
}

// ---------------- tf32 mma GEMM (unchanged from round 3) ----------------
template<bool RELU, bool RESID, bool RND>
__global__ __launch_bounds__(256)
void tc_gemm(const float* __restrict__ A, const float* __restrict__ Bw,
             const float* __restrict__ bias, const float* __restrict__ resid,
             float* __restrict__ C, int M, int N, int K)
{
    extern __shared__ float smemf[];
    const uint32_t sb = smem_u32(smemf);

    const int tid = threadIdx.x;
    const int wid = tid >> 5;
    const int lane = tid & 31;
    const int bx = blockIdx.x, by = blockIdx.y;

    const float* Ag = A + (size_t)by * BM * K;
    const float* Bg = Bw + (size_t)bx * BN * K;

    const int grow = tid >> 3;
    const int gc4  = tid & 7;

    auto issue_chunk = [&](int chunk, int buf) {
        const int k0 = chunk * BKC;
        const uint32_t base = sb + (uint32_t)buf * (2u * TILE_BYTES);
#pragma unroll
        for (int p = 0; p < 4; p++) {
            const int r = p * 32 + grow;
            cp_async16(base + (uint32_t)r * (LDS_STRIDE*4) + (uint32_t)gc4 * 16,
                       Ag + (size_t)r * K + k0 + gc4 * 4);
        }
#pragma unroll
        for (int p = 0; p < 4; p++) {
            const int r = p * 32 + grow;
            cp_async16(base + TILE_BYTES + (uint32_t)r * (LDS_STRIDE*4) + (uint32_t)gc4 * 16,
                       Bg + (size_t)r * K + k0 + gc4 * 4);
        }
        cp_commit();
    };

    const int nc = K / BKC;
    issue_chunk(0, 0);
    if (nc > 1) issue_chunk(1, 1);

    const int wm = (wid >> 2) * 64;
    const int wn = (wid & 3) * 32;
    const int qr = lane >> 2;
    const int qc = lane & 3;

    float acc[4][4][4];
#pragma unroll
    for (int mi = 0; mi < 4; mi++)
#pragma unroll
        for (int ni = 0; ni < 4; ni++)
#pragma unroll
            for (int e = 0; e < 4; e++) acc[mi][ni][e] = 0.f;

    for (int c = 0; c < nc; c++) {
        if (c + 1 < nc) asm volatile("cp.async.wait_group 1;" ::: "memory");
        else            asm volatile("cp.async.wait_group 0;" ::: "memory");
        __syncthreads();

        const uint32_t* sAu = reinterpret_cast<const uint32_t*>(smemf) + (c & 1) * BUF_FLOATS;
        const uint32_t* sBu = sAu + TILE_FLOATS;

#pragma unroll
        for (int ks = 0; ks < 4; ks++) {
            const int kk = ks * 8 + qc;
            uint32_t bfr[4][2];
#pragma unroll
            for (int ni = 0; ni < 4; ni++) {
                const int n = wn + ni * 8 + qr;
                bfr[ni][0] = sBu[n * LDS_STRIDE + kk];
                bfr[ni][1] = sBu[n * LDS_STRIDE + kk + 4];
            }
#pragma unroll
            for (int mi = 0; mi < 4; mi++) {
                const int r = wm + mi * 16 + qr;
                const uint32_t a0 = sAu[r * LDS_STRIDE + kk];
                const uint32_t a1 = sAu[(r + 8) * LDS_STRIDE + kk];
                const uint32_t a2 = sAu[r * LDS_STRIDE + kk + 4];
                const uint32_t a3 = sAu[(r + 8) * LDS_STRIDE + kk + 4];
#pragma unroll
                for (int ni = 0; ni < 4; ni++) {
                    asm volatile(
                        "mma.sync.aligned.m16n8k8.row.col.f32.tf32.tf32.f32 "
                        "{%0,%1,%2,%3}, {%4,%5,%6,%7}, {%8,%9}, {%0,%1,%2,%3};"
                        : "+f"(acc[mi][ni][0]), "+f"(acc[mi][ni][1]),
                          "+f"(acc[mi][ni][2]), "+f"(acc[mi][ni][3])
                        : "r"(a0), "r"(a1), "r"(a2), "r"(a3),
                          "r"(bfr[ni][0]), "r"(bfr[ni][1]));
                }
            }
        }
        __syncthreads();
        if (c + 2 < nc) issue_chunk(c + 2, c & 1);
    }

#pragma unroll
    for (int mi = 0; mi < 4; mi++) {
#pragma unroll
        for (int ni = 0; ni < 4; ni++) {
            const int r0 = by * BM + wm + mi * 16 + qr;
            const int c0 = bx * BN + wn + ni * 8 + qc * 2;
            const float2 bv = *(const float2*)(bias + c0);
#pragma unroll
            for (int hrow = 0; hrow < 2; hrow++) {
                const int rr = r0 + hrow * 8;
                float v0 = acc[mi][ni][hrow * 2 + 0] + bv.x;
                float v1 = acc[mi][ni][hrow * 2 + 1] + bv.y;
                if (RESID) {
                    const float2 rv = *(const float2*)(resid + (size_t)rr * N + c0);
                    v0 += rv.x; v1 += rv.y;
                }
                if (RELU) { v0 = fmaxf(v0, 0.f); v1 = fmaxf(v1, 0.f); }
                if (RND)  { v0 = tf32r(v0); v1 = tf32r(v1); }
                *(float2*)(C + (size_t)rr * N + c0) = make_float2(v0, v1);
            }
        }
    }
}

// ---------------- flash attention via tf32 mma ----------------
// CTA: 128 queries of one (b,h). 8 warps x 16 query rows. Key tiles of 64.
// QK^T in 3xtf32 (near-fp32 scores); softmax fp32; PV in tf32.
// Output written tf32-rounded (feeds out-proj GEMM directly).
__global__ __launch_bounds__(256, 1)
void attn_mma_kernel(const float* __restrict__ qkv, float* __restrict__ outr)
{
    extern __shared__ float sm[];
    const int qblk = blockIdx.x;
    const int h = blockIdx.y;
    const int b = blockIdx.z;
    const int tid = threadIdx.x;
    const int w = tid >> 5;
    const int lane = tid & 31;
    const int gr = lane >> 2;
    const int tg = lane & 3;
    const int qbase = qblk * 128;

    // ---- stage Q tile (raw fp32) ----
    {
        const int row = tid >> 1, c0 = (tid & 1) * 32;
        const float* src = qkv + ((size_t)(b * SS + qbase + row)) * (3 * DD) + h * DK + c0;
        float* dst = sm + SQ_OFF + row * AQ_STRIDE + c0;
#pragma unroll
        for (int i = 0; i < 8; i++)
            *(float4*)(dst + i * 4) = *(const float4*)(src + i * 4);
    }
    __syncthreads();

    // ---- Q fragments (scaled, hi/lo split) ----
    float qa[8][4], ql[8][4];
    {
        const float* qw = sm + SQ_OFF + (w * 16) * AQ_STRIDE;
#pragma unroll
        for (int kc = 0; kc < 8; kc++) {
            float r[4];
            r[0] = qw[gr * AQ_STRIDE + kc * 8 + tg]       * INV_SCALE;
            r[1] = qw[(gr + 8) * AQ_STRIDE + kc * 8 + tg] * INV_SCALE;
            r[2] = qw[gr * AQ_STRIDE + kc * 8 + tg + 4]       * INV_SCALE;
            r[3] = qw[(gr + 8) * AQ_STRIDE + kc * 8 + tg + 4] * INV_SCALE;
#pragma unroll
            for (int e = 0; e < 4; e++) {
                qa[kc][e] = tf32r(r[e]);
                ql[kc][e] = tf32r(r[e] - qa[kc][e]);
            }
        }
    }

    float o[8][4];
#pragma unroll
    for (int nb = 0; nb < 8; nb++)
#pragma unroll
        for (int e = 0; e < 4; e++) o[nb][e] = 0.f;
    float m0 = -1e30f, m1 = -1e30f, l0 = 0.f, l1 = 0.f;

    const int ntiles = 2 * qblk + 2;
    const int wrow_min = qbase + w * 16;

    for (int kt = 0; kt < ntiles; kt++) {
        __syncthreads();
        // ---- load K (hi/lo) and V (rounded) tile ----
        {
            const int row = tid >> 2, c0 = (tid & 3) * 16;
            const float* kb = qkv + ((size_t)(b * SS + kt * 64 + row)) * (3 * DD) + DD + h * DK + c0;
            const float* vb = kb + DD;
            float* dk  = sm + SK_OFF  + row * AQ_STRIDE + c0;
            float* dkl = sm + SKL_OFF + row * AQ_STRIDE + c0;
            float* dv  = sm + SV_OFF  + row * AV_STRIDE + c0;
#pragma unroll
            for (int i = 0; i < 4; i++) {
                float4 kv = *(const float4*)(kb + i * 4);
                float4 hi = make_float4(tf32r(kv.x), tf32r(kv.y), tf32r(kv.z), tf32r(kv.w));
                float4 lo = make_float4(tf32r(kv.x - hi.x), tf32r(kv.y - hi.y),
                                        tf32r(kv.z - hi.z), tf32r(kv.w - hi.w));
                *(float4*)(dk + i * 4)  = hi;
                *(float4*)(dkl + i * 4) = lo;
                float4 vv = *(const float4*)(vb + i * 4);
                *(float4*)(dv + i * 4) = make_float4(tf32r(vv.x), tf32r(vv.y),
                                                     tf32r(vv.z), tf32r(vv.w));
            }
        }
        __syncthreads();

        if (kt * 64 > wrow_min + 15) continue;   // tile fully above diagonal for this warp

        // ---- S = Q K^T (3xtf32) ----
        float s[8][4];
#pragma unroll
        for (int nb = 0; nb < 8; nb++) {
            s[nb][0] = s[nb][1] = s[nb][2] = s[nb][3] = 0.f;
#pragma unroll
            for (int kc = 0; kc < 8; kc++) {
                const int krow = (nb * 8 + gr) * AQ_STRIDE + kc * 8 + tg;
                const float kh0 = sm[SK_OFF + krow];
                const float kh1 = sm[SK_OFF + krow + 4];
                const float kl0 = sm[SKL_OFF + krow];
                const float kl1 = sm[SKL_OFF + krow + 4];
                mma8(s[nb], qa[kc][0], qa[kc][1], qa[kc][2], qa[kc][3], kh0, kh1);
                mma8(s[nb], qa[kc][0], qa[kc][1], qa[kc][2], qa[kc][3], kl0, kl1);
                mma8(s[nb], ql[kc][0], ql[kc][1], ql[kc][2], ql[kc][3], kh0, kh1);
            }
        }

        const int row0 = wrow_min + gr;
        const int row1 = row0 + 8;
        if (kt * 64 + 63 > wrow_min) {   // diagonal region: mask
#pragma unroll
            for (int nb = 0; nb < 8; nb++) {
                const int col = kt * 64 + nb * 8 + 2 * tg;
                if (col > row0)     s[nb][0] = -1e30f;
                if (col + 1 > row0) s[nb][1] = -1e30f;
                if (col > row1)     s[nb][2] = -1e30f;
                if (col + 1 > row1) s[nb][3] = -1e30f;
            }
        }

        // ---- online softmax ----
        float lm0 = -1e30f, lm1 = -1e30f;
#pragma unroll
        for (int nb = 0; nb < 8; nb++) {
            lm0 = fmaxf(lm0, fmaxf(s[nb][0], s[nb][1]));
            lm1 = fmaxf(lm1, fmaxf(s[nb][2], s[nb][3]));
        }
        lm0 = fmaxf(lm0, __shfl_xor_sync(0xffffffffu, lm0, 1));
        lm0 = fmaxf(lm0, __shfl_xor_sync(0xffffffffu, lm0, 2));
        lm1 = fmaxf(lm1, __shfl_xor_sync(0xffffffffu, lm1, 1));
        lm1 = fmaxf(lm1, __shfl_xor_sync(0xffffffffu, lm1, 2));
        const float nm0 = fmaxf(m0, lm0), nm1 = fmaxf(m1, lm1);
        const float c0 = __expf(m0 - nm0), c1 = __expf(m1 - nm1);
        m0 = nm0; m1 = nm1;

        float ps0 = 0.f, ps1 = 0.f;
#pragma unroll
        for (int nb = 0; nb < 8; nb++) {
            s[nb][0] = __expf(s[nb][0] - m0);
            s[nb][1] = __expf(s[nb][1] - m0);
            s[nb][2] = __expf(s[nb][2] - m1);
            s[nb][3] = __expf(s[nb][3] - m1);
            ps0 += s[nb][0] + s[nb][1];
            ps1 += s[nb][2] + s[nb][3];
        }
        ps0 += __shfl_xor_sync(0xffffffffu, ps0, 1);
        ps0 += __shfl_xor_sync(0xffffffffu, ps0, 2);
        ps1 += __shfl_xor_sync(0xffffffffu, ps1, 1);
        ps1 += __shfl_xor_sync(0xffffffffu, ps1, 2);
        l0 = l0 * c0 + ps0;
        l1 = l1 * c1 + ps1;
#pragma unroll
        for (int nb = 0; nb < 8; nb++) {
            o[nb][0] *= c0; o[nb][1] *= c0;
            o[nb][2] *= c1; o[nb][3] *= c1;
        }

        // ---- P -> smem (tf32) ----
        float* pw = sm + SP_OFF + w * (16 * AQ_STRIDE);
#pragma unroll
        for (int nb = 0; nb < 8; nb++) {
            *(float2*)(pw + gr * AQ_STRIDE + nb * 8 + 2 * tg) =
                make_float2(tf32r(s[nb][0]), tf32r(s[nb][1]));
            *(float2*)(pw + (gr + 8) * AQ_STRIDE + nb * 8 + 2 * tg) =
                make_float2(tf32r(s[nb][2]), tf32r(s[nb][3]));
        }
        __syncwarp();

        // ---- O += P V ----
#pragma unroll
        for (int kc = 0; kc < 8; kc++) {
            const float pa0 = pw[gr * AQ_STRIDE + kc * 8 + tg];
            const float pa1 = pw[(gr + 8) * AQ_STRIDE + kc * 8 + tg];
            const float pa2 = pw[gr * AQ_STRIDE + kc * 8 + tg + 4];
            const float pa3 = pw[(gr + 8) * AQ_STRIDE + kc * 8 + tg + 4];
#pragma unroll
            for (int nb = 0; nb < 8; nb++) {
                const float vb0 = sm[SV_OFF + (kc * 8 + tg) * AV_STRIDE + nb * 8 + gr];
                const float vb1 = sm[SV_OFF + (kc * 8 + tg + 4) * AV_STRIDE + nb * 8 + gr];
                mma8(o[nb], pa0, pa1, pa2, pa3, vb0, vb1);
            }
        }
        __syncwarp();
    }

    // ---- epilogue: normalize + tf32-round + store ----
    const float il0 = 1.f / l0, il1 = 1.f / l1;
    const int grow0 = b * SS + qbase + w * 16 + gr;
    float* d0 = outr + (size_t)grow0 * DD + h * DK;
    float* d1 = d0 + 8 * DD;
#pragma unroll
    for (int nb = 0; nb < 8; nb++) {
        *(float2*)(d0 + nb * 8 + 2 * tg) =
            make_float2(tf32r(o[nb][0] * il0), tf32r(o[nb][1] * il0));
        *(float2*)(d1 + nb * 8 + 2 * tg) =
            make_float2(tf32r(o[nb][2] * il1), tf32r(o[nb][3] * il1));
    }
}

// ---------------- LayerNorm (dual output) ----------------
__global__ __launch_bounds__(256)
void ln_kernel(const float* __restrict__ in, const float* __restrict__ gamma,
               const float* __restrict__ beta, float* __restrict__ out,
               float* __restrict__ outr)
{
    const int row = blockIdx.x;
    const int t = threadIdx.x;
    const float* xr = in + (size_t)row * DD;

    const float x0 = xr[t];
    const float x1 = xr[t + 256];
    float s  = x0 + x1;
    float sq = x0 * x0 + x1 * x1;

#pragma unroll
    for (int off = 16; off > 0; off >>= 1) {
        s  += __shfl_xor_sync(0xffffffffu, s,  off);
        sq += __shfl_xor_sync(0xffffffffu, sq, off);
    }
    __shared__ float ss[8], sqq[8];
    if ((t & 31) == 0) { ss[t >> 5] = s; sqq[t >> 5] = sq; }
    __syncthreads();
    float ts = 0.f, tq = 0.f;
#pragma unroll
    for (int wq = 0; wq < 8; wq++) { ts += ss[wq]; tq += sqq[wq]; }

    const float mean = ts * (1.f / DD);
    const float var  = tq * (1.f / DD) - mean * mean;
    const float rstd = rsqrtf(var + EPS);

    float* orow = out + (size_t)row * DD;
    float* orr  = outr + (size_t)row * DD;
    const float v0 = (x0 - mean) * rstd * gamma[t]       + beta[t];
    const float v1 = (x1 - mean) * rstd * gamma[t + 256] + beta[t + 256];
    orow[t]       = v0;
    orow[t + 256] = v1;
    orr[t]        = tf32r(v0);
    orr[t + 256]  = tf32r(v1);
}

// ---------------- driver ----------------
extern "C" void kernel_launch(void* const* d_in, const int* in_sizes, int n_in,
                              void* d_out, int out_size)
{
    const float* x      = (const float*)d_in[0];
    const float* qkv_w  = (const float*)d_in[1];
    const float* qkv_b  = (const float*)d_in[2];
    const float* out_w  = (const float*)d_in[3];
    const float* out_b  = (const float*)d_in[4];
    const float* ln1_g  = (const float*)d_in[5];
    const float* ln1_b  = (const float*)d_in[6];
    const float* mlp_w1 = (const float*)d_in[7];
    const float* mlp_b1 = (const float*)d_in[8];
    const float* mlp_w2 = (const float*)d_in[9];
    const float* mlp_b2 = (const float*)d_in[10];
    const float* ln2_g  = (const float*)d_in[11];
    const float* ln2_b  = (const float*)d_in[12];
    float* outp = (float*)d_out;

    float *px, *pxr, *pqkv, *pattnr, *ph, *pt2;
    float *pqkvwt, *poutwt, *pw1t, *pw2t;
    cudaGetSymbolAddress((void**)&px,    g_x);
    cudaGetSymbolAddress((void**)&pxr,   g_xr);
    cudaGetSymbolAddress((void**)&pqkv,  g_qkv);
    cudaGetSymbolAddress((void**)&pattnr,g_attnr);
    cudaGetSymbolAddress((void**)&ph,    g_h);
    cudaGetSymbolAddress((void**)&pt2,   g_t2);
    cudaGetSymbolAddress((void**)&pqkvwt,g_qkv_wt);
    cudaGetSymbolAddress((void**)&poutwt,g_out_wt);
    cudaGetSymbolAddress((void**)&pw1t,  g_w1t);
    cudaGetSymbolAddress((void**)&pw2t,  g_w2t);

    cudaFuncSetAttribute(tc_gemm<false,false,false>, cudaFuncAttributeMaxDynamicSharedMemorySize, GSMEM_BYTES);
    cudaFuncSetAttribute(tc_gemm<false,true,false>,  cudaFuncAttributeMaxDynamicSharedMemorySize, GSMEM_BYTES);
    cudaFuncSetAttribute(tc_gemm<true,false,true>,   cudaFuncAttributeMaxDynamicSharedMemorySize, GSMEM_BYTES);
    cudaFuncSetAttribute(attn_mma_kernel, cudaFuncAttributeMaxDynamicSharedMemorySize, ASMEM_BYTES);

    transpose_rnd<<<dim3(3*DD/32, DD/32, LL), dim3(32,8)>>>(qkv_w, pqkvwt, DD, 3*DD);
    transpose_rnd<<<dim3(DD/32,   DD/32, LL), dim3(32,8)>>>(out_w, poutwt, DD, DD);
    transpose_rnd<<<dim3(DFF/32,  DD/32, LL), dim3(32,8)>>>(mlp_w1, pw1t, DD, DFF);
    transpose_rnd<<<dim3(DD/32,  DFF/32, LL), dim3(32,8)>>>(mlp_w2, pw2t, DFF, DD);

    const int nX = MM * DD;
    copy_round_kernel<<<(nX/4 + 255)/256, 256>>>((const float4*)x, (float4*)px, (float4*)pxr, nX/4);

    for (int i = 0; i < LL; i++) {
        tc_gemm<false,false,false><<<dim3(3*DD/BN, MM/BM), 256, GSMEM_BYTES>>>(
            pxr, pqkvwt + (size_t)i * 3*DD*DD, qkv_b + (size_t)i * 3*DD,
            nullptr, pqkv, MM, 3*DD, DD);

        attn_mma_kernel<<<dim3(SS/128, HH, BB), 256, ASMEM_BYTES>>>(pqkv, pattnr);

        tc_gemm<false,true,false><<<dim3(DD/BN, MM/BM), 256, GSMEM_BYTES>>>(
            pattnr, poutwt + (size_t)i * DD*DD, out_b + (size_t)i * DD,
            px, pt2, MM, DD, DD);

        ln_kernel<<<MM, 256>>>(pt2, ln1_g + (size_t)i * DD, ln1_b + (size_t)i * DD, px, pxr);

        tc_gemm<true,false,true><<<dim3(DFF/BN, MM/BM), 256, GSMEM_BYTES>>>(
            pxr, pw1t + (size_t)i * DFF*DD, mlp_b1 + (size_t)i * DFF,
            nullptr, ph, MM, DFF, DD);

        tc_gemm<false,true,false><<<dim3(DD/BN, MM/BM), 256, GSMEM_BYTES>>>(
            ph, pw2t + (size_t)i * DD*DFF, mlp_b2 + (size_t)i * DD,
            px, pt2, MM, DD, DFF);

        float* lnout = (i == LL - 1) ? outp : px;
        ln_kernel<<<MM, 256>>>(pt2, ln2_g + (size_t)i * DD, ln2_b + (size_t)i * DD, lnout, pxr);
    }
}

// round 7
// speedup vs baseline: 5.6033x; 1.3315x over previous
#include <cuda_runtime.h>
#include <cuda_fp16.h>
#include <cuda_bf16.h>
#include <math.h>
#include <cstdint>

// Problem constants
#define BB 8
#define SS 1024
#define DD 512
#define HH 8
#define DK 64
#define DFF 2048
#define LL 6
#define MM (BB*SS)          // 8192 rows
#define EPS 1e-5f
#define INV_SCALE 0.125f

// fp16 GEMM tiling: 128x128 CTA tile, K-chunk 32 halves
#define BM 128
#define BN 128
#define BKC 32
#define ROW_U32 20                      // 16 data u32 + 4 pad (conflict-free)
#define TILE_U32 (128*ROW_U32)          // 2560
#define TILE_BYTES_H (TILE_U32*4)       // 10240
#define BUF_U32 (2*TILE_U32)            // A+B per buffer
#define GSMEM_BYTES (2*2*TILE_BYTES_H)  // 40960

// Attention smem layout (floats) — unchanged tf32 internals
#define AQ_STRIDE 68
#define AV_STRIDE 72
#define SQ_OFF  0
#define SK_OFF  8704
#define SKL_OFF 13056
#define SV_OFF  17408
#define SP_OFF  22016
#define ASMEM_FLOATS 30720
#define ASMEM_BYTES (ASMEM_FLOATS*4)    // 122880

// ---------------- scratch ----------------
__device__ float  g_x[MM*DD];           // exact fp32 activations
__device__ __half g_xh[MM*DD];          // half copy (GEMM A operand)
__device__ float  g_qkv[MM*3*DD];       // fp32 (attention needs precision)
__device__ __half g_attnh[MM*DD];       // attention output (half)
__device__ __half g_hh[MM*DFF];         // MLP hidden (half)
__device__ float  g_t2[MM*DD];
// transposed half weights, [N,K] K-major
__device__ __half g_qkv_wt[LL*3*DD*DD];
__device__ __half g_out_wt[LL*DD*DD];
__device__ __half g_w1t[LL*DFF*DD];
__device__ __half g_w2t[LL*DD*DFF];

// ---------------- helpers ----------------
__device__ __forceinline__ float tf32r(float x) {
    uint32_t u; asm("cvt.rna.tf32.f32 %0, %1;" : "=r"(u) : "f"(x));
    return __uint_as_float(u);
}
__device__ __forceinline__ uint32_t smem_u32(const void* p) {
    uint32_t a;
    asm("{ .reg .u64 t; cvta.to.shared.u64 t, %1; cvt.u32.u64 %0, t; }" : "=r"(a) : "l"(p));
    return a;
}
__device__ __forceinline__ void cp_async16(uint32_t dst, const void* src) {
    asm volatile("cp.async.cg.shared.global [%0], [%1], 16;" :: "r"(dst), "l"(src));
}
__device__ __forceinline__ void cp_commit() {
    asm volatile("cp.async.commit_group;" ::: "memory");
}
__device__ __forceinline__ void mma8(float c[4], const float a0, const float a1,
                                     const float a2, const float a3,
                                     const float b0, const float b1) {
    asm volatile(
        "mma.sync.aligned.m16n8k8.row.col.f32.tf32.tf32.f32 "
        "{%0,%1,%2,%3}, {%4,%5,%6,%7}, {%8,%9}, {%0,%1,%2,%3};"
        : "+f"(c[0]), "+f"(c[1]), "+f"(c[2]), "+f"(c[3])
        : "r"(__float_as_uint(a0)), "r"(__float_as_uint(a1)),
          "r"(__float_as_uint(a2)), "r"(__float_as_uint(a3)),
          "r"(__float_as_uint(b0)), "r"(__float_as_uint(b1)));
}
__device__ __forceinline__ void mma16h(float c[4], uint32_t a0, uint32_t a1,
                                       uint32_t a2, uint32_t a3,
                                       uint32_t b0, uint32_t b1) {
    asm volatile(
        "mma.sync.aligned.m16n8k16.row.col.f32.f16.f16.f32 "
        "{%0,%1,%2,%3}, {%4,%5,%6,%7}, {%8,%9}, {%0,%1,%2,%3};"
        : "+f"(c[0]), "+f"(c[1]), "+f"(c[2]), "+f"(c[3])
        : "r"(a0), "r"(a1), "r"(a2), "r"(a3), "r"(b0), "r"(b1));
}

// ---------------- elementwise ----------------
__global__ void copy_half_kernel(const float4* __restrict__ src, float4* __restrict__ dst,
                                 __half2* __restrict__ dsth, int n4) {
    int i = blockIdx.x * blockDim.x + threadIdx.x;
    if (i < n4) {
        float4 v = src[i];
        dst[i] = v;
        dsth[2*i]   = __floats2half2_rn(v.x, v.y);
        dsth[2*i+1] = __floats2half2_rn(v.z, v.w);
    }
}

// transpose + fp16 convert: W[L][K][N] -> Wt[L][N][K]
__global__ void transpose_h(const float* __restrict__ W, __half* __restrict__ Wt,
                            int K, int N) {
    __shared__ float t[32][33];
    const int l = blockIdx.z;
    const float* Wl = W + (size_t)l * K * N;
    __half* Wtl = Wt + (size_t)l * K * N;
    const int k0 = blockIdx.y * 32, n0 = blockIdx.x * 32;
    const int tx = threadIdx.x, ty = threadIdx.y;
#pragma unroll
    for (int i = 0; i < 32; i += 8)
        t[ty + i][tx] = Wl[(size_t)(k0 + ty + i) * N + n0 + tx];
    __syncthreads();
#pragma unroll
    for (int i = 0; i < 32; i += 8)
        Wtl[(size_t)(n0 + ty + i) * K + k0 + tx] = __float2half(t[tx][ty + i]);
}

// ---------------- fp16 mma GEMM: C[M,N] = A[M,K] @ Wt[N,K]^T ----------
// A, Wt half; accumulate fp32. 128x128 CTA tile, K-chunks of 32,
// cp.async double-buffered. 8 warps, 64x32 warp tile, m16n8k16 fragments.
template<bool RELU, bool RESID, bool HOUT>
__global__ __launch_bounds__(256)
void tc_gemm(const __half* __restrict__ A, const __half* __restrict__ Bw,
             const float* __restrict__ bias, const float* __restrict__ resid,
             void* __restrict__ Cv, int M, int N, int K)
{
    extern __shared__ float smemf[];
    const uint32_t sb = smem_u32(smemf);

    const int tid = threadIdx.x;
    const int wid = tid >> 5;
    const int lane = tid & 31;
    const int bx = blockIdx.x, by = blockIdx.y;

    const __half* Ag = A + (size_t)by * BM * K;
    const __half* Bg = Bw + (size_t)bx * BN * K;

    // each thread: 2 A chunks + 2 B chunks of 16B per tile
    auto issue_chunk = [&](int chunk, int buf) {
        const int k0 = chunk * BKC;
        const uint32_t base = sb + (uint32_t)buf * (2u * TILE_BYTES_H);
#pragma unroll
        for (int p = 0; p < 2; p++) {
            const int idx = tid * 2 + p;        // 0..511
            const int row = idx >> 2;
            const int j = idx & 3;
            cp_async16(base + (uint32_t)row * (ROW_U32*4) + (uint32_t)j * 16,
                       Ag + (size_t)row * K + k0 + j * 8);
        }
#pragma unroll
        for (int p = 0; p < 2; p++) {
            const int idx = tid * 2 + p;
            const int row = idx >> 2;
            const int j = idx & 3;
            cp_async16(base + TILE_BYTES_H + (uint32_t)row * (ROW_U32*4) + (uint32_t)j * 16,
                       Bg + (size_t)row * K + k0 + j * 8);
        }
        cp_commit();
    };

    const int nc = K / BKC;
    issue_chunk(0, 0);
    if (nc > 1) issue_chunk(1, 1);

    const int wm = (wid >> 2) * 64;
    const int wn = (wid & 3) * 32;
    const int qr = lane >> 2;
    const int qc = lane & 3;

    float acc[4][4][4];
#pragma unroll
    for (int mi = 0; mi < 4; mi++)
#pragma unroll
        for (int ni = 0; ni < 4; ni++)
#pragma unroll
            for (int e = 0; e < 4; e++) acc[mi][ni][e] = 0.f;

    for (int c = 0; c < nc; c++) {
        if (c + 1 < nc) asm volatile("cp.async.wait_group 1;" ::: "memory");
        else            asm volatile("cp.async.wait_group 0;" ::: "memory");
        __syncthreads();

        const uint32_t* sAu = reinterpret_cast<const uint32_t*>(smemf) + (c & 1) * BUF_U32;
        const uint32_t* sBu = sAu + TILE_U32;

#pragma unroll
        for (int ks = 0; ks < 2; ks++) {
            const int col = ks * 8 + qc;
            uint32_t bfr[4][2];
#pragma unroll
            for (int ni = 0; ni < 4; ni++) {
                const int n = wn + ni * 8 + qr;
                bfr[ni][0] = sBu[n * ROW_U32 + col];
                bfr[ni][1] = sBu[n * ROW_U32 + col + 4];
            }
#pragma unroll
            for (int mi = 0; mi < 4; mi++) {
                const int r = wm + mi * 16 + qr;
                const uint32_t a0 = sAu[r * ROW_U32 + col];
                const uint32_t a1 = sAu[(r + 8) * ROW_U32 + col];
                const uint32_t a2 = sAu[r * ROW_U32 + col + 4];
                const uint32_t a3 = sAu[(r + 8) * ROW_U32 + col + 4];
#pragma unroll
                for (int ni = 0; ni < 4; ni++)
                    mma16h(acc[mi][ni], a0, a1, a2, a3, bfr[ni][0], bfr[ni][1]);
            }
        }
        __syncthreads();
        if (c + 2 < nc) issue_chunk(c + 2, c & 1);
    }

    // epilogue: bias (+resid) (relu), float2 or half2 stores
#pragma unroll
    for (int mi = 0; mi < 4; mi++) {
#pragma unroll
        for (int ni = 0; ni < 4; ni++) {
            const int r0 = by * BM + wm + mi * 16 + qr;
            const int c0 = bx * BN + wn + ni * 8 + qc * 2;
            const float2 bv = *(const float2*)(bias + c0);
#pragma unroll
            for (int hrow = 0; hrow < 2; hrow++) {
                const int rr = r0 + hrow * 8;
                float v0 = acc[mi][ni][hrow * 2 + 0] + bv.x;
                float v1 = acc[mi][ni][hrow * 2 + 1] + bv.y;
                if (RESID) {
                    const float2 rv = *(const float2*)(resid + (size_t)rr * N + c0);
                    v0 += rv.x; v1 += rv.y;
                }
                if (RELU) { v0 = fmaxf(v0, 0.f); v1 = fmaxf(v1, 0.f); }
                if (HOUT) {
                    *(__half2*)((__half*)Cv + (size_t)rr * N + c0) = __floats2half2_rn(v0, v1);
                } else {
                    *(float2*)((float*)Cv + (size_t)rr * N + c0) = make_float2(v0, v1);
                }
            }
        }
    }
}

// ---------------- flash attention via tf32 mma (output -> half) ----------------
__global__ __launch_bounds__(256, 1)
void attn_mma_kernel(const float* __restrict__ qkv, __half* __restrict__ outh)
{
    extern __shared__ float sm[];
    const int qblk = blockIdx.x;
    const int h = blockIdx.y;
    const int b = blockIdx.z;
    const int tid = threadIdx.x;
    const int w = tid >> 5;
    const int lane = tid & 31;
    const int gr = lane >> 2;
    const int tg = lane & 3;
    const int qbase = qblk * 128;

    // stage Q tile (raw fp32)
    {
        const int row = tid >> 1, c0 = (tid & 1) * 32;
        const float* src = qkv + ((size_t)(b * SS + qbase + row)) * (3 * DD) + h * DK + c0;
        float* dst = sm + SQ_OFF + row * AQ_STRIDE + c0;
#pragma unroll
        for (int i = 0; i < 8; i++)
            *(float4*)(dst + i * 4) = *(const float4*)(src + i * 4);
    }
    __syncthreads();

    // Q fragments (scaled, hi/lo split)
    float qa[8][4], ql[8][4];
    {
        const float* qw = sm + SQ_OFF + (w * 16) * AQ_STRIDE;
#pragma unroll
        for (int kc = 0; kc < 8; kc++) {
            float r[4];
            r[0] = qw[gr * AQ_STRIDE + kc * 8 + tg]       * INV_SCALE;
            r[1] = qw[(gr + 8) * AQ_STRIDE + kc * 8 + tg] * INV_SCALE;
            r[2] = qw[gr * AQ_STRIDE + kc * 8 + tg + 4]       * INV_SCALE;
            r[3] = qw[(gr + 8) * AQ_STRIDE + kc * 8 + tg + 4] * INV_SCALE;
#pragma unroll
            for (int e = 0; e < 4; e++) {
                qa[kc][e] = tf32r(r[e]);
                ql[kc][e] = tf32r(r[e] - qa[kc][e]);
            }
        }
    }

    float o[8][4];
#pragma unroll
    for (int nb = 0; nb < 8; nb++)
#pragma unroll
        for (int e = 0; e < 4; e++) o[nb][e] = 0.f;
    float m0 = -1e30f, m1 = -1e30f, l0 = 0.f, l1 = 0.f;

    const int ntiles = 2 * qblk + 2;
    const int wrow_min = qbase + w * 16;

    for (int kt = 0; kt < ntiles; kt++) {
        __syncthreads();
        // load K (hi/lo) and V (rounded) tile
        {
            const int row = tid >> 2, c0 = (tid & 3) * 16;
            const float* kb = qkv + ((size_t)(b * SS + kt * 64 + row)) * (3 * DD) + DD + h * DK + c0;
            const float* vb = kb + DD;
            float* dk  = sm + SK_OFF  + row * AQ_STRIDE + c0;
            float* dkl = sm + SKL_OFF + row * AQ_STRIDE + c0;
            float* dv  = sm + SV_OFF  + row * AV_STRIDE + c0;
#pragma unroll
            for (int i = 0; i < 4; i++) {
                float4 kv = *(const float4*)(kb + i * 4);
                float4 hi = make_float4(tf32r(kv.x), tf32r(kv.y), tf32r(kv.z), tf32r(kv.w));
                float4 lo = make_float4(tf32r(kv.x - hi.x), tf32r(kv.y - hi.y),
                                        tf32r(kv.z - hi.z), tf32r(kv.w - hi.w));
                *(float4*)(dk + i * 4)  = hi;
                *(float4*)(dkl + i * 4) = lo;
                float4 vv = *(const float4*)(vb + i * 4);
                *(float4*)(dv + i * 4) = make_float4(tf32r(vv.x), tf32r(vv.y),
                                                     tf32r(vv.z), tf32r(vv.w));
            }
        }
        __syncthreads();

        if (kt * 64 > wrow_min + 15) continue;

        // S = Q K^T (3xtf32)
        float s[8][4];
#pragma unroll
        for (int nb = 0; nb < 8; nb++) {
            s[nb][0] = s[nb][1] = s[nb][2] = s[nb][3] = 0.f;
#pragma unroll
            for (int kc = 0; kc < 8; kc++) {
                const int krow = (nb * 8 + gr) * AQ_STRIDE + kc * 8 + tg;
                const float kh0 = sm[SK_OFF + krow];
                const float kh1 = sm[SK_OFF + krow + 4];
                const float kl0 = sm[SKL_OFF + krow];
                const float kl1 = sm[SKL_OFF + krow + 4];
                mma8(s[nb], qa[kc][0], qa[kc][1], qa[kc][2], qa[kc][3], kh0, kh1);
                mma8(s[nb], qa[kc][0], qa[kc][1], qa[kc][2], qa[kc][3], kl0, kl1);
                mma8(s[nb], ql[kc][0], ql[kc][1], ql[kc][2], ql[kc][3], kh0, kh1);
            }
        }

        const int row0 = wrow_min + gr;
        const int row1 = row0 + 8;
        if (kt * 64 + 63 > wrow_min) {
#pragma unroll
            for (int nb = 0; nb < 8; nb++) {
                const int col = kt * 64 + nb * 8 + 2 * tg;
                if (col > row0)     s[nb][0] = -1e30f;
                if (col + 1 > row0) s[nb][1] = -1e30f;
                if (col > row1)     s[nb][2] = -1e30f;
                if (col + 1 > row1) s[nb][3] = -1e30f;
            }
        }

        // online softmax
        float lm0 = -1e30f, lm1 = -1e30f;
#pragma unroll
        for (int nb = 0; nb < 8; nb++) {
            lm0 = fmaxf(lm0, fmaxf(s[nb][0], s[nb][1]));
            lm1 = fmaxf(lm1, fmaxf(s[nb][2], s[nb][3]));
        }
        lm0 = fmaxf(lm0, __shfl_xor_sync(0xffffffffu, lm0, 1));
        lm0 = fmaxf(lm0, __shfl_xor_sync(0xffffffffu, lm0, 2));
        lm1 = fmaxf(lm1, __shfl_xor_sync(0xffffffffu, lm1, 1));
        lm1 = fmaxf(lm1, __shfl_xor_sync(0xffffffffu, lm1, 2));
        const float nm0 = fmaxf(m0, lm0), nm1 = fmaxf(m1, lm1);
        const float c0 = __expf(m0 - nm0), c1 = __expf(m1 - nm1);
        m0 = nm0; m1 = nm1;

        float ps0 = 0.f, ps1 = 0.f;
#pragma unroll
        for (int nb = 0; nb < 8; nb++) {
            s[nb][0] = __expf(s[nb][0] - m0);
            s[nb][1] = __expf(s[nb][1] - m0);
            s[nb][2] = __expf(s[nb][2] - m1);
            s[nb][3] = __expf(s[nb][3] - m1);
            ps0 += s[nb][0] + s[nb][1];
            ps1 += s[nb][2] + s[nb][3];
        }
        ps0 += __shfl_xor_sync(0xffffffffu, ps0, 1);
        ps0 += __shfl_xor_sync(0xffffffffu, ps0, 2);
        ps1 += __shfl_xor_sync(0xffffffffu, ps1, 1);
        ps1 += __shfl_xor_sync(0xffffffffu, ps1, 2);
        l0 = l0 * c0 + ps0;
        l1 = l1 * c1 + ps1;
#pragma unroll
        for (int nb = 0; nb < 8; nb++) {
            o[nb][0] *= c0; o[nb][1] *= c0;
            o[nb][2] *= c1; o[nb][3] *= c1;
        }

        // P -> smem (tf32)
        float* pw = sm + SP_OFF + w * (16 * AQ_STRIDE);
#pragma unroll
        for (int nb = 0; nb < 8; nb++) {
            *(float2*)(pw + gr * AQ_STRIDE + nb * 8 + 2 * tg) =
                make_float2(tf32r(s[nb][0]), tf32r(s[nb][1]));
            *(float2*)(pw + (gr + 8) * AQ_STRIDE + nb * 8 + 2 * tg) =
                make_float2(tf32r(s[nb][2]), tf32r(s[nb][3]));
        }
        __syncwarp();

        // O += P V
#pragma unroll
        for (int kc = 0; kc < 8; kc++) {
            const float pa0 = pw[gr * AQ_STRIDE + kc * 8 + tg];
            const float pa1 = pw[(gr + 8) * AQ_STRIDE + kc * 8 + tg];
            const float pa2 = pw[gr * AQ_STRIDE + kc * 8 + tg + 4];
            const float pa3 = pw[(gr + 8) * AQ_STRIDE + kc * 8 + tg + 4];
#pragma unroll
            for (int nb = 0; nb < 8; nb++) {
                const float vb0 = sm[SV_OFF + (kc * 8 + tg) * AV_STRIDE + nb * 8 + gr];
                const float vb1 = sm[SV_OFF + (kc * 8 + tg + 4) * AV_STRIDE + nb * 8 + gr];
                mma8(o[nb], pa0, pa1, pa2, pa3, vb0, vb1);
            }
        }
        __syncwarp();
    }

    // epilogue: normalize + half store
    const float il0 = 1.f / l0, il1 = 1.f / l1;
    const int grow0 = b * SS + qbase + w * 16 + gr;
    __half* d0 = outh + (size_t)grow0 * DD + h * DK;
    __half* d1 = d0 + 8 * DD;
#pragma unroll
    for (int nb = 0; nb < 8; nb++) {
        *(__half2*)(d0 + nb * 8 + 2 * tg) = __floats2half2_rn(o[nb][0] * il0, o[nb][1] * il0);
        *(__half2*)(d1 + nb * 8 + 2 * tg) = __floats2half2_rn(o[nb][2] * il1, o[nb][3] * il1);
    }
}

// ---------------- LayerNorm (fp32 out + half out) ----------------
__global__ __launch_bounds__(256)
void ln_kernel(const float* __restrict__ in, const float* __restrict__ gamma,
               const float* __restrict__ beta, float* __restrict__ out,
               __half* __restrict__ outh)
{
    const int row = blockIdx.x;
    const int t = threadIdx.x;
    const float* xr = in + (size_t)row * DD;

    const float2 xv = *(const float2*)(xr + 2 * t);
    float s  = xv.x + xv.y;
    float sq = xv.x * xv.x + xv.y * xv.y;

#pragma unroll
    for (int off = 16; off > 0; off >>= 1) {
        s  += __shfl_xor_sync(0xffffffffu, s,  off);
        sq += __shfl_xor_sync(0xffffffffu, sq, off);
    }
    __shared__ float ss[8], sqq[8];
    if ((t & 31) == 0) { ss[t >> 5] = s; sqq[t >> 5] = sq; }
    __syncthreads();
    float ts = 0.f, tq = 0.f;
#pragma unroll
    for (int wq = 0; wq < 8; wq++) { ts += ss[wq]; tq += sqq[wq]; }

    const float mean = ts * (1.f / DD);
    const float var  = tq * (1.f / DD) - mean * mean;
    const float rstd = rsqrtf(var + EPS);

    const float2 gv = *(const float2*)(gamma + 2 * t);
    const float2 bv = *(const float2*)(beta + 2 * t);
    const float v0 = (xv.x - mean) * rstd * gv.x + bv.x;
    const float v1 = (xv.y - mean) * rstd * gv.y + bv.y;
    *(float2*)(out + (size_t)row * DD + 2 * t) = make_float2(v0, v1);
    *(__half2*)(outh + (size_t)row * DD + 2 * t) = __floats2half2_rn(v0, v1);
}

// ---------------- driver ----------------
extern "C" void kernel_launch(void* const* d_in, const int* in_sizes, int n_in,
                              void* d_out, int out_size)
{
    const float* x      = (const float*)d_in[0];
    const float* qkv_w  = (const float*)d_in[1];
    const float* qkv_b  = (const float*)d_in[2];
    const float* out_w  = (const float*)d_in[3];
    const float* out_b  = (const float*)d_in[4];
    const float* ln1_g  = (const float*)d_in[5];
    const float* ln1_b  = (const float*)d_in[6];
    const float* mlp_w1 = (const float*)d_in[7];
    const float* mlp_b1 = (const float*)d_in[8];
    const float* mlp_w2 = (const float*)d_in[9];
    const float* mlp_b2 = (const float*)d_in[10];
    const float* ln2_g  = (const float*)d_in[11];
    const float* ln2_b  = (const float*)d_in[12];
    float* outp = (float*)d_out;

    float *px, *pqkv, *pt2;
    __half *pxh, *pattnh, *phh, *pqkvwt, *poutwt, *pw1t, *pw2t;
    cudaGetSymbolAddress((void**)&px,    g_x);
    cudaGetSymbolAddress((void**)&pxh,   g_xh);
    cudaGetSymbolAddress((void**)&pqkv,  g_qkv);
    cudaGetSymbolAddress((void**)&pattnh,g_attnh);
    cudaGetSymbolAddress((void**)&phh,   g_hh);
    cudaGetSymbolAddress((void**)&pt2,   g_t2);
    cudaGetSymbolAddress((void**)&pqkvwt,g_qkv_wt);
    cudaGetSymbolAddress((void**)&poutwt,g_out_wt);
    cudaGetSymbolAddress((void**)&pw1t,  g_w1t);
    cudaGetSymbolAddress((void**)&pw2t,  g_w2t);

    cudaFuncSetAttribute(tc_gemm<false,false,false>, cudaFuncAttributeMaxDynamicSharedMemorySize, GSMEM_BYTES);
    cudaFuncSetAttribute(tc_gemm<false,true,false>,  cudaFuncAttributeMaxDynamicSharedMemorySize, GSMEM_BYTES);
    cudaFuncSetAttribute(tc_gemm<true,false,true>,   cudaFuncAttributeMaxDynamicSharedMemorySize, GSMEM_BYTES);
    cudaFuncSetAttribute(attn_mma_kernel, cudaFuncAttributeMaxDynamicSharedMemorySize, ASMEM_BYTES);

    transpose_h<<<dim3(3*DD/32, DD/32, LL), dim3(32,8)>>>(qkv_w, pqkvwt, DD, 3*DD);
    transpose_h<<<dim3(DD/32,   DD/32, LL), dim3(32,8)>>>(out_w, poutwt, DD, DD);
    transpose_h<<<dim3(DFF/32,  DD/32, LL), dim3(32,8)>>>(mlp_w1, pw1t, DD, DFF);
    transpose_h<<<dim3(DD/32,  DFF/32, LL), dim3(32,8)>>>(mlp_w2, pw2t, DFF, DD);

    const int nX = MM * DD;
    copy_half_kernel<<<(nX/4 + 255)/256, 256>>>((const float4*)x, (float4*)px,
                                                (__half2*)pxh, nX/4);

    for (int i = 0; i < LL; i++) {
        // QKV: [8192,512] x [512,1536] (+bias) -> fp32
        tc_gemm<false,false,false><<<dim3(3*DD/BN, MM/BM), 256, GSMEM_BYTES>>>(
            pxh, pqkvwt + (size_t)i * 3*DD*DD, qkv_b + (size_t)i * 3*DD,
            nullptr, pqkv, MM, 3*DD, DD);

        attn_mma_kernel<<<dim3(SS/128, HH, BB), 256, ASMEM_BYTES>>>(pqkv, pattnh);

        // out-proj + residual(x) -> fp32 t2
        tc_gemm<false,true,false><<<dim3(DD/BN, MM/BM), 256, GSMEM_BYTES>>>(
            pattnh, poutwt + (size_t)i * DD*DD, out_b + (size_t)i * DD,
            px, pt2, MM, DD, DD);

        ln_kernel<<<MM, 256>>>(pt2, ln1_g + (size_t)i * DD, ln1_b + (size_t)i * DD, px, pxh);

        // MLP1 + ReLU -> half hh
        tc_gemm<true,false,true><<<dim3(DFF/BN, MM/BM), 256, GSMEM_BYTES>>>(
            pxh, pw1t + (size_t)i * DFF*DD, mlp_b1 + (size_t)i * DFF,
            nullptr, phh, MM, DFF, DD);

        // MLP2 + residual(x) -> fp32 t2
        tc_gemm<false,true,false><<<dim3(DD/BN, MM/BM), 256, GSMEM_BYTES>>>(
            phh, pw2t + (size_t)i * DD*DFF, mlp_b2 + (size_t)i * DD,
            px, pt2, MM, DD, DFF);

        float* lnout = (i == LL - 1) ? outp : px;
        ln_kernel<<<MM, 256>>>(pt2, ln2_g + (size_t)i * DD, ln2_b + (size_t)i * DD, lnout, pxh);
    }
}

// round 9
// speedup vs baseline: 7.0707x; 1.2619x over previous
#include <cuda_runtime.h>
#include <cuda_fp16.h>
#include <math.h>
#include <cstdint>

// Problem constants
#define BB 8
#define SS 1024
#define DD 512
#define HH 8
#define DK 64
#define DFF 2048
#define LL 6
#define MM (BB*SS)          // 8192 rows
#define EPS 1e-5f
#define INV_SCALE 0.125f

// fp16 GEMM tiling: 128x128 CTA tile, K-chunk 32 halves
#define BM 128
#define BN 128
#define BKC 32
#define ROW_U32 20                      // 16 data u32 + 4 pad (conflict-free)
#define TILE_U32 (128*ROW_U32)          // 2560
#define TILE_BYTES_H (TILE_U32*4)       // 10240
#define BUF_U32 (2*TILE_U32)            // A+B per buffer
#define GSMEM_BYTES (2*2*TILE_BYTES_H)  // 40960

// fp16 attention smem strides (u32 units)
#define AST 36                          // 72 halves per row (64 data + 8 pad)

// ---------------- scratch ----------------
__device__ float  g_x[MM*DD];           // exact fp32 activations
__device__ __half g_xh[MM*DD];          // half copy (GEMM A operand)
__device__ __half g_qkvh[MM*3*DD];      // QKV in half
__device__ __half g_attnh[MM*DD];       // attention output (half)
__device__ __half g_hh[MM*DFF];         // MLP hidden (half)
__device__ float  g_t2[MM*DD];
// transposed half weights, [N,K] K-major
__device__ __half g_qkv_wt[LL*3*DD*DD];
__device__ __half g_out_wt[LL*DD*DD];
__device__ __half g_w1t[LL*DFF*DD];
__device__ __half g_w2t[LL*DD*DFF];

// ---------------- helpers ----------------
__device__ __forceinline__ uint32_t smem_u32(const void* p) {
    uint32_t a;
    asm("{ .reg .u64 t; cvta.to.shared.u64 t, %1; cvt.u32.u64 %0, t; }" : "=r"(a) : "l"(p));
    return a;
}
__device__ __forceinline__ void cp_async16(uint32_t dst, const void* src) {
    asm volatile("cp.async.cg.shared.global [%0], [%1], 16;" :: "r"(dst), "l"(src));
}
__device__ __forceinline__ void cp_commit() {
    asm volatile("cp.async.commit_group;" ::: "memory");
}
__device__ __forceinline__ void mma16h(float c[4], uint32_t a0, uint32_t a1,
                                       uint32_t a2, uint32_t a3,
                                       uint32_t b0, uint32_t b1) {
    asm volatile(
        "mma.sync.aligned.m16n8k16.row.col.f32.f16.f16.f32 "
        "{%0,%1,%2,%3}, {%4,%5,%6,%7}, {%8,%9}, {%0,%1,%2,%3};"
        : "+f"(c[0]), "+f"(c[1]), "+f"(c[2]), "+f"(c[3])
        : "r"(a0), "r"(a1), "r"(a2), "r"(a3), "r"(b0), "r"(b1));
}
__device__ __forceinline__ uint32_t h2u(__half2 h) { return *(uint32_t*)&h; }

// ---------------- elementwise ----------------
__global__ void copy_half_kernel(const float4* __restrict__ src, float4* __restrict__ dst,
                                 __half2* __restrict__ dsth, int n4) {
    int i = blockIdx.x * blockDim.x + threadIdx.x;
    if (i < n4) {
        float4 v = src[i];
        dst[i] = v;
        dsth[2*i]   = __floats2half2_rn(v.x, v.y);
        dsth[2*i+1] = __floats2half2_rn(v.z, v.w);
    }
}

// transpose + fp16 convert: W[L][K][N] -> Wt[L][N][K]
__global__ void transpose_h(const float* __restrict__ W, __half* __restrict__ Wt,
                            int K, int N) {
    __shared__ float t[32][33];
    const int l = blockIdx.z;
    const float* Wl = W + (size_t)l * K * N;
    __half* Wtl = Wt + (size_t)l * K * N;
    const int k0 = blockIdx.y * 32, n0 = blockIdx.x * 32;
    const int tx = threadIdx.x, ty = threadIdx.y;
#pragma unroll
    for (int i = 0; i < 32; i += 8)
        t[ty + i][tx] = Wl[(size_t)(k0 + ty + i) * N + n0 + tx];
    __syncthreads();
#pragma unroll
    for (int i = 0; i < 32; i += 8)
        Wtl[(size_t)(n0 + ty + i) * K + k0 + tx] = __float2half(t[tx][ty + i]);
}

// ---------------- fp16 mma GEMM: C[M,N] = A[M,K] @ Wt[N,K]^T ----------
template<bool RELU, bool RESID, bool HOUT>
__global__ __launch_bounds__(256)
void tc_gemm(const __half* __restrict__ A, const __half* __restrict__ Bw,
             const float* __restrict__ bias, const float* __restrict__ resid,
             void* __restrict__ Cv, int M, int N, int K)
{
    extern __shared__ float smemf[];
    const uint32_t sb = smem_u32(smemf);

    const int tid = threadIdx.x;
    const int wid = tid >> 5;
    const int lane = tid & 31;
    const int bx = blockIdx.x, by = blockIdx.y;

    const __half* Ag = A + (size_t)by * BM * K;
    const __half* Bg = Bw + (size_t)bx * BN * K;

    auto issue_chunk = [&](int chunk, int buf) {
        const int k0 = chunk * BKC;
        const uint32_t base = sb + (uint32_t)buf * (2u * TILE_BYTES_H);
#pragma unroll
        for (int p = 0; p < 2; p++) {
            const int idx = tid * 2 + p;
            const int row = idx >> 2;
            const int j = idx & 3;
            cp_async16(base + (uint32_t)row * (ROW_U32*4) + (uint32_t)j * 16,
                       Ag + (size_t)row * K + k0 + j * 8);
        }
#pragma unroll
        for (int p = 0; p < 2; p++) {
            const int idx = tid * 2 + p;
            const int row = idx >> 2;
            const int j = idx & 3;
            cp_async16(base + TILE_BYTES_H + (uint32_t)row * (ROW_U32*4) + (uint32_t)j * 16,
                       Bg + (size_t)row * K + k0 + j * 8);
        }
        cp_commit();
    };

    const int nc = K / BKC;
    issue_chunk(0, 0);
    if (nc > 1) issue_chunk(1, 1);

    const int wm = (wid >> 2) * 64;
    const int wn = (wid & 3) * 32;
    const int qr = lane >> 2;
    const int qc = lane & 3;

    float acc[4][4][4];
#pragma unroll
    for (int mi = 0; mi < 4; mi++)
#pragma unroll
        for (int ni = 0; ni < 4; ni++)
#pragma unroll
            for (int e = 0; e < 4; e++) acc[mi][ni][e] = 0.f;

    for (int c = 0; c < nc; c++) {
        if (c + 1 < nc) asm volatile("cp.async.wait_group 1;" ::: "memory");
        else            asm volatile("cp.async.wait_group 0;" ::: "memory");
        __syncthreads();

        const uint32_t* sAu = reinterpret_cast<const uint32_t*>(smemf) + (c & 1) * BUF_U32;
        const uint32_t* sBu = sAu + TILE_U32;

#pragma unroll
        for (int ks = 0; ks < 2; ks++) {
            const int col = ks * 8 + qc;
            uint32_t bfr[4][2];
#pragma unroll
            for (int ni = 0; ni < 4; ni++) {
                const int n = wn + ni * 8 + qr;
                bfr[ni][0] = sBu[n * ROW_U32 + col];
                bfr[ni][1] = sBu[n * ROW_U32 + col + 4];
            }
#pragma unroll
            for (int mi = 0; mi < 4; mi++) {
                const int r = wm + mi * 16 + qr;
                const uint32_t a0 = sAu[r * ROW_U32 + col];
                const uint32_t a1 = sAu[(r + 8) * ROW_U32 + col];
                const uint32_t a2 = sAu[r * ROW_U32 + col + 4];
                const uint32_t a3 = sAu[(r + 8) * ROW_U32 + col + 4];
#pragma unroll
                for (int ni = 0; ni < 4; ni++)
                    mma16h(acc[mi][ni], a0, a1, a2, a3, bfr[ni][0], bfr[ni][1]);
            }
        }
        __syncthreads();
        if (c + 2 < nc) issue_chunk(c + 2, c & 1);
    }

#pragma unroll
    for (int mi = 0; mi < 4; mi++) {
#pragma unroll
        for (int ni = 0; ni < 4; ni++) {
            const int r0 = by * BM + wm + mi * 16 + qr;
            const int c0 = bx * BN + wn + ni * 8 + qc * 2;
            const float2 bv = *(const float2*)(bias + c0);
#pragma unroll
            for (int hrow = 0; hrow < 2; hrow++) {
                const int rr = r0 + hrow * 8;
                float v0 = acc[mi][ni][hrow * 2 + 0] + bv.x;
                float v1 = acc[mi][ni][hrow * 2 + 1] + bv.y;
                if (RESID) {
                    const float2 rv = *(const float2*)(resid + (size_t)rr * N + c0);
                    v0 += rv.x; v1 += rv.y;
                }
                if (RELU) { v0 = fmaxf(v0, 0.f); v1 = fmaxf(v1, 0.f); }
                if (HOUT) {
                    *(__half2*)((__half*)Cv + (size_t)rr * N + c0) = __floats2half2_rn(v0, v1);
                } else {
                    *(float2*)((float*)Cv + (size_t)rr * N + c0) = make_float2(v0, v1);
                }
            }
        }
    }
}

// ---------------- flash attention, full fp16 mma ----------------
// CTA: 128 queries of one (b,h). 8 warps x 16 query rows. Key tiles of 64.
// QK^T fp16 m16n8k16, softmax fp32, PV fp16 with P kept in registers.
__global__ __launch_bounds__(256, 1)
void attn_h_kernel(const __half* __restrict__ qkvh, __half* __restrict__ outh)
{
    __shared__ uint32_t sQ[128*AST];    // 18432 B
    __shared__ uint32_t sK[64*AST];     //  9216 B
    __shared__ uint32_t sVt[64*AST];    //  9216 B (V transposed: [d][key])

    const int qblk = blockIdx.x;
    const int h = blockIdx.y;
    const int b = blockIdx.z;
    const int tid = threadIdx.x;
    const int w = tid >> 5;
    const int lane = tid & 31;
    const int gr = lane >> 2;
    const int tg = lane & 3;
    const int qbase = qblk * 128;

    // stage Q tile (half, row-major [128][64])
    {
        const int row = tid >> 1, seg = tid & 1;
        const __half* src = qkvh + ((size_t)(b * SS + qbase + row)) * (3 * DD) + h * DK + seg * 32;
        uint4* dst = (uint4*)(sQ + row * AST + seg * 16);
        const uint4* s4 = (const uint4*)src;
#pragma unroll
        for (int i = 0; i < 4; i++) dst[i] = s4[i];
    }
    __syncthreads();

    // Q A-fragments: 4 k-chunks of 16 halves
    uint32_t qa[4][4];
    {
        const uint32_t* qw = sQ + (w * 16) * AST;
#pragma unroll
        for (int c = 0; c < 4; c++) {
            qa[c][0] = qw[gr * AST + 8 * c + tg];
            qa[c][1] = qw[(gr + 8) * AST + 8 * c + tg];
            qa[c][2] = qw[gr * AST + 8 * c + tg + 4];
            qa[c][3] = qw[(gr + 8) * AST + 8 * c + tg + 4];
        }
    }

    float o[8][4];
#pragma unroll
    for (int nd = 0; nd < 8; nd++)
#pragma unroll
        for (int e = 0; e < 4; e++) o[nd][e] = 0.f;
    float m0 = -1e30f, m1 = -1e30f, l0 = 0.f, l1 = 0.f;

    const int ntiles = 2 * qblk + 2;
    const int wrow_min = qbase + w * 16;

    for (int kt = 0; kt < ntiles; kt++) {
        __syncthreads();
        // load K tile [64 keys][64 dims] and V transposed [64 dims][64 keys]
        {
            const int row = tid >> 2, seg = tid & 3;
            const __half* kb = qkvh + ((size_t)(b * SS + kt * 64 + row)) * (3 * DD)
                             + DD + h * DK + seg * 16;
            uint4* dk = (uint4*)(sK + row * AST + seg * 8);
            dk[0] = ((const uint4*)kb)[0];
            dk[1] = ((const uint4*)kb)[1];

            const __half* vb = kb + DD;
            __half tmp[16];
            *(uint4*)tmp       = ((const uint4*)vb)[0];
            *(uint4*)(tmp + 8) = ((const uint4*)vb)[1];
            __half* vt = (__half*)sVt;
#pragma unroll
            for (int i = 0; i < 16; i++)
                vt[(seg * 16 + i) * (2 * AST) + row] = tmp[i];
        }
        __syncthreads();

        if (kt * 64 > wrow_min + 15) continue;

        // S = Q K^T (fp16), scale 1/8
        float s[8][4];
#pragma unroll
        for (int nb = 0; nb < 8; nb++) {
            s[nb][0] = s[nb][1] = s[nb][2] = s[nb][3] = 0.f;
#pragma unroll
            for (int c = 0; c < 4; c++) {
                const uint32_t* kr = sK + (nb * 8 + gr) * AST + 8 * c + tg;
                mma16h(s[nb], qa[c][0], qa[c][1], qa[c][2], qa[c][3], kr[0], kr[4]);
            }
#pragma unroll
            for (int e = 0; e < 4; e++) s[nb][e] *= INV_SCALE;
        }

        const int row0 = wrow_min + gr;
        const int row1 = row0 + 8;
        if (kt * 64 + 63 > wrow_min) {
#pragma unroll
            for (int nb = 0; nb < 8; nb++) {
                const int col = kt * 64 + nb * 8 + 2 * tg;
                if (col > row0)     s[nb][0] = -1e30f;
                if (col + 1 > row0) s[nb][1] = -1e30f;
                if (col > row1)     s[nb][2] = -1e30f;
                if (col + 1 > row1) s[nb][3] = -1e30f;
            }
        }

        // online softmax
        float lm0 = -1e30f, lm1 = -1e30f;
#pragma unroll
        for (int nb = 0; nb < 8; nb++) {
            lm0 = fmaxf(lm0, fmaxf(s[nb][0], s[nb][1]));
            lm1 = fmaxf(lm1, fmaxf(s[nb][2], s[nb][3]));
        }
        lm0 = fmaxf(lm0, __shfl_xor_sync(0xffffffffu, lm0, 1));
        lm0 = fmaxf(lm0, __shfl_xor_sync(0xffffffffu, lm0, 2));
        lm1 = fmaxf(lm1, __shfl_xor_sync(0xffffffffu, lm1, 1));
        lm1 = fmaxf(lm1, __shfl_xor_sync(0xffffffffu, lm1, 2));
        const float nm0 = fmaxf(m0, lm0), nm1 = fmaxf(m1, lm1);
        const float c0 = __expf(m0 - nm0), c1 = __expf(m1 - nm1);
        m0 = nm0; m1 = nm1;

        float ps0 = 0.f, ps1 = 0.f;
#pragma unroll
        for (int nb = 0; nb < 8; nb++) {
            s[nb][0] = __expf(s[nb][0] - m0);
            s[nb][1] = __expf(s[nb][1] - m0);
            s[nb][2] = __expf(s[nb][2] - m1);
            s[nb][3] = __expf(s[nb][3] - m1);
            ps0 += s[nb][0] + s[nb][1];
            ps1 += s[nb][2] + s[nb][3];
        }
        ps0 += __shfl_xor_sync(0xffffffffu, ps0, 1);
        ps0 += __shfl_xor_sync(0xffffffffu, ps0, 2);
        ps1 += __shfl_xor_sync(0xffffffffu, ps1, 1);
        ps1 += __shfl_xor_sync(0xffffffffu, ps1, 2);
        l0 = l0 * c0 + ps0;
        l1 = l1 * c1 + ps1;
#pragma unroll
        for (int nd = 0; nd < 8; nd++) {
            o[nd][0] *= c0; o[nd][1] *= c0;
            o[nd][2] *= c1; o[nd][3] *= c1;
        }

        // P -> fp16 register fragments
        uint32_t p01[8], p23[8];
#pragma unroll
        for (int nb = 0; nb < 8; nb++) {
            p01[nb] = h2u(__floats2half2_rn(s[nb][0], s[nb][1]));
            p23[nb] = h2u(__floats2half2_rn(s[nb][2], s[nb][3]));
        }

        // O += P V (B from transposed V tile)
#pragma unroll
        for (int c = 0; c < 4; c++) {
            const uint32_t a0 = p01[2 * c], a1 = p23[2 * c];
            const uint32_t a2 = p01[2 * c + 1], a3 = p23[2 * c + 1];
#pragma unroll
            for (int nd = 0; nd < 8; nd++) {
                const uint32_t* vr = sVt + (nd * 8 + gr) * AST + 8 * c + tg;
                mma16h(o[nd], a0, a1, a2, a3, vr[0], vr[4]);
            }
        }
    }

    // epilogue: normalize + half store
    const float il0 = 1.f / l0, il1 = 1.f / l1;
    const int grow0 = b * SS + qbase + w * 16 + gr;
    __half* d0 = outh + (size_t)grow0 * DD + h * DK;
    __half* d1 = d0 + 8 * DD;
#pragma unroll
    for (int nd = 0; nd < 8; nd++) {
        *(__half2*)(d0 + nd * 8 + 2 * tg) = __floats2half2_rn(o[nd][0] * il0, o[nd][1] * il0);
        *(__half2*)(d1 + nd * 8 + 2 * tg) = __floats2half2_rn(o[nd][2] * il1, o[nd][3] * il1);
    }
}

// ---------------- LayerNorm (fp32 out + half out) ----------------
__global__ __launch_bounds__(256)
void ln_kernel(const float* __restrict__ in, const float* __restrict__ gamma,
               const float* __restrict__ beta, float* __restrict__ out,
               __half* __restrict__ outh)
{
    const int row = blockIdx.x;
    const int t = threadIdx.x;
    const float* xr = in + (size_t)row * DD;

    const float2 xv = *(const float2*)(xr + 2 * t);
    float s  = xv.x + xv.y;
    float sq = xv.x * xv.x + xv.y * xv.y;

#pragma unroll
    for (int off = 16; off > 0; off >>= 1) {
        s  += __shfl_xor_sync(0xffffffffu, s,  off);
        sq += __shfl_xor_sync(0xffffffffu, sq, off);
    }
    __shared__ float ss[8], sqq[8];
    if ((t & 31) == 0) { ss[t >> 5] = s; sqq[t >> 5] = sq; }
    __syncthreads();
    float ts = 0.f, tq = 0.f;
#pragma unroll
    for (int wq = 0; wq < 8; wq++) { ts += ss[wq]; tq += sqq[wq]; }

    const float mean = ts * (1.f / DD);
    const float var  = tq * (1.f / DD) - mean * mean;
    const float rstd = rsqrtf(var + EPS);

    const float2 gv = *(const float2*)(gamma + 2 * t);
    const float2 bv = *(const float2*)(beta + 2 * t);
    const float v0 = (xv.x - mean) * rstd * gv.x + bv.x;
    const float v1 = (xv.y - mean) * rstd * gv.y + bv.y;
    *(float2*)(out + (size_t)row * DD + 2 * t) = make_float2(v0, v1);
    *(__half2*)(outh + (size_t)row * DD + 2 * t) = __floats2half2_rn(v0, v1);
}

// ---------------- driver ----------------
extern "C" void kernel_launch(void* const* d_in, const int* in_sizes, int n_in,
                              void* d_out, int out_size)
{
    const float* x      = (const float*)d_in[0];
    const float* qkv_w  = (const float*)d_in[1];
    const float* qkv_b  = (const float*)d_in[2];
    const float* out_w  = (const float*)d_in[3];
    const float* out_b  = (const float*)d_in[4];
    const float* ln1_g  = (const float*)d_in[5];
    const float* ln1_b  = (const float*)d_in[6];
    const float* mlp_w1 = (const float*)d_in[7];
    const float* mlp_b1 = (const float*)d_in[8];
    const float* mlp_w2 = (const float*)d_in[9];
    const float* mlp_b2 = (const float*)d_in[10];
    const float* ln2_g  = (const float*)d_in[11];
    const float* ln2_b  = (const float*)d_in[12];
    float* outp = (float*)d_out;

    float *px, *pt2;
    __half *pxh, *pqkvh, *pattnh, *phh, *pqkvwt, *poutwt, *pw1t, *pw2t;
    cudaGetSymbolAddress((void**)&px,    g_x);
    cudaGetSymbolAddress((void**)&pxh,   g_xh);
    cudaGetSymbolAddress((void**)&pqkvh, g_qkvh);
    cudaGetSymbolAddress((void**)&pattnh,g_attnh);
    cudaGetSymbolAddress((void**)&phh,   g_hh);
    cudaGetSymbolAddress((void**)&pt2,   g_t2);
    cudaGetSymbolAddress((void**)&pqkvwt,g_qkv_wt);
    cudaGetSymbolAddress((void**)&poutwt,g_out_wt);
    cudaGetSymbolAddress((void**)&pw1t,  g_w1t);
    cudaGetSymbolAddress((void**)&pw2t,  g_w2t);

    cudaFuncSetAttribute(tc_gemm<false,false,true>, cudaFuncAttributeMaxDynamicSharedMemorySize, GSMEM_BYTES);
    cudaFuncSetAttribute(tc_gemm<false,true,false>, cudaFuncAttributeMaxDynamicSharedMemorySize, GSMEM_BYTES);
    cudaFuncSetAttribute(tc_gemm<true,false,true>,  cudaFuncAttributeMaxDynamicSharedMemorySize, GSMEM_BYTES);

    transpose_h<<<dim3(3*DD/32, DD/32, LL), dim3(32,8)>>>(qkv_w, pqkvwt, DD, 3*DD);
    transpose_h<<<dim3(DD/32,   DD/32, LL), dim3(32,8)>>>(out_w, poutwt, DD, DD);
    transpose_h<<<dim3(DFF/32,  DD/32, LL), dim3(32,8)>>>(mlp_w1, pw1t, DD, DFF);
    transpose_h<<<dim3(DD/32,  DFF/32, LL), dim3(32,8)>>>(mlp_w2, pw2t, DFF, DD);

    const int nX = MM * DD;
    copy_half_kernel<<<(nX/4 + 255)/256, 256>>>((const float4*)x, (float4*)px,
                                                (__half2*)pxh, nX/4);

    for (int i = 0; i < LL; i++) {
        // QKV: [8192,512] x [512,1536] (+bias) -> half
        tc_gemm<false,false,true><<<dim3(3*DD/BN, MM/BM), 256, GSMEM_BYTES>>>(
            pxh, pqkvwt + (size_t)i * 3*DD*DD, qkv_b + (size_t)i * 3*DD,
            nullptr, pqkvh, MM, 3*DD, DD);

        attn_h_kernel<<<dim3(SS/128, HH, BB), 256>>>(pqkvh, pattnh);

        // out-proj + residual(x) -> fp32 t2
        tc_gemm<false,true,false><<<dim3(DD/BN, MM/BM), 256, GSMEM_BYTES>>>(
            pattnh, poutwt + (size_t)i * DD*DD, out_b + (size_t)i * DD,
            px, pt2, MM, DD, DD);

        ln_kernel<<<MM, 256>>>(pt2, ln1_g + (size_t)i * DD, ln1_b + (size_t)i * DD, px, pxh);

        // MLP1 + ReLU -> half hh
        tc_gemm<true,false,true><<<dim3(DFF/BN, MM/BM), 256, GSMEM_BYTES>>>(
            pxh, pw1t + (size_t)i * DFF*DD, mlp_b1 + (size_t)i * DFF,
            nullptr, phh, MM, DFF, DD);

        // MLP2 + residual(x) -> fp32 t2
        tc_gemm<false,true,false><<<dim3(DD/BN, MM/BM), 256, GSMEM_BYTES>>>(
            phh, pw2t + (size_t)i * DD*DFF, mlp_b2 + (size_t)i * DD,
            px, pt2, MM, DD, DFF);

        float* lnout = (i == LL - 1) ? outp : px;
        ln_kernel<<<MM, 256>>>(pt2, ln2_g + (size_t)i * DD, ln2_b + (size_t)i * DD, lnout, pxh);
    }
}